// round 7
// baseline (speedup 1.0000x reference)
#include <cuda_runtime.h>

#define Hdim 128
#define NNODES 50000
#define NEDGES 800000
#define TILE 64
#define LDA 68   // padded feature-major stride; mult of 4 => 16B-aligned row quads

__device__ int   g_is64;
__device__ float g_mi[(long long)NNODES * Hdim];  // segment-summed m_i scratch
__device__ float g_P [(long long)NNODES * Hdim];  // h @ We1[0:128]   + be1
__device__ float g_Q [(long long)NNODES * Hdim];  // h @ We1[128:256]

// ---------- f32x2 helpers ----------
__device__ __forceinline__ unsigned long long pk2(float lo, float hi) {
    unsigned long long r;
    asm("mov.b64 %0, {%1,%2};" : "=l"(r) : "f"(lo), "f"(hi));
    return r;
}
__device__ __forceinline__ void upk2(unsigned long long v, float& lo, float& hi) {
    asm("mov.b64 {%0,%1}, %2;" : "=f"(lo), "=f"(hi) : "l"(v));
}
#define FMA2(d, a, b) asm("fma.rn.f32x2 %0, %1, %2, %0;" : "+l"(d) : "l"(a), "l"(b))

__device__ __forceinline__ void red_add_v4(float* p, float a, float b, float c, float d) {
    asm volatile("red.global.add.v4.f32 [%0], {%1,%2,%3,%4};"
                 :: "l"(p), "f"(a), "f"(b), "f"(c), "f"(d) : "memory");
}

__device__ __forceinline__ float silu_f(float v) { return v / (1.0f + __expf(-v)); }

// ---------- GEMM tile: C[64 rows x 128 cols] = A[64 x K] * W[K x 128] (+ bias) ----------
// A feature-major in smem: A[k*LDA + row]. Thread (tx,ty): rows r0..r0+7 as 4 packed
// pairs (2 x LDS.128 broadcast), cols tx*4..tx*4+3 (1 x LDG.128, L1-hit).
template <int K>
__device__ __forceinline__ void gemm_tile(const float* __restrict__ As,
                                          const float* __restrict__ W,
                                          const float* __restrict__ bias,
                                          unsigned long long acc[4][4],
                                          int tx, int r0) {
    float4 b4 = bias ? __ldg((const float4*)(bias + tx * 4))
                     : make_float4(0.f, 0.f, 0.f, 0.f);
#pragma unroll
    for (int i = 0; i < 4; i++) {
        acc[i][0] = pk2(b4.x, b4.x);
        acc[i][1] = pk2(b4.y, b4.y);
        acc[i][2] = pk2(b4.z, b4.z);
        acc[i][3] = pk2(b4.w, b4.w);
    }
#pragma unroll 4
    for (int k = 0; k < K; k++) {
        float4 w = __ldg((const float4*)(W + (long long)k * Hdim + tx * 4));
        unsigned long long w0 = pk2(w.x, w.x);
        unsigned long long w1 = pk2(w.y, w.y);
        unsigned long long w2 = pk2(w.z, w.z);
        unsigned long long w3 = pk2(w.w, w.w);
        const float* ak = As + k * LDA + r0;
        ulonglong2 aP = *(const ulonglong2*)(ak);
        ulonglong2 aQ = *(const ulonglong2*)(ak + 4);
        unsigned long long a2[4] = {aP.x, aP.y, aQ.x, aQ.y};
#pragma unroll
        for (int i = 0; i < 4; i++) {
            FMA2(acc[i][0], a2[i], w0);
            FMA2(acc[i][1], a2[i], w1);
            FMA2(acc[i][2], a2[i], w2);
            FMA2(acc[i][3], a2[i], w3);
        }
    }
}

// ---------- index dtype detection (int32 vs int64) ----------
__global__ void detect_kernel(const int* ei32) {
    if (blockIdx.x == 0 && threadIdx.x == 0) {
        int f = 1;
        for (int i = 0; i < 1024; i++) {
            if (ei32[2 * i + 1] != 0) { f = 0; break; }
        }
        g_is64 = f;
    }
}

// ---------- init: zero m_i scratch, seed out_x = x ----------
__global__ void init_kernel(const float* __restrict__ x, float* __restrict__ out_x) {
    long long i = (long long)blockIdx.x * blockDim.x + threadIdx.x;
    if (i < (long long)NNODES * Hdim) g_mi[i] = 0.0f;
    if (i < (long long)NNODES * 3)    out_x[i] = x[i];
}

// ---------- prep: P = h @ We1[0:128] + be1 ; Q = h @ We1[128:256] ----------
__global__ void __launch_bounds__(256) prep_kernel(
    const float* __restrict__ h,
    const float* __restrict__ We1, const float* __restrict__ be1) {
    extern __shared__ float sm[];
    float* As = sm;  // 128 * LDA

    const int tid = threadIdx.x;
    const int tx = tid & 31, ty = tid >> 5;
    const int r0 = ty * 8;
    const int nb = blockIdx.x * TILE;

    for (int e = ty; e < TILE; e += 8) {
        const int node = nb + e;
        const int d0 = tx * 4;
        float4 hv = make_float4(0.f, 0.f, 0.f, 0.f);
        if (node < NNODES) hv = __ldg((const float4*)(h + (long long)node * Hdim + d0));
        As[(d0 + 0) * LDA + e] = hv.x;
        As[(d0 + 1) * LDA + e] = hv.y;
        As[(d0 + 2) * LDA + e] = hv.z;
        As[(d0 + 3) * LDA + e] = hv.w;
    }
    __syncthreads();

    unsigned long long acc[4][4];

    gemm_tile<128>(As, We1, be1, acc, tx, r0);
#pragma unroll
    for (int i = 0; i < 4; i++) {
        const int n0 = nb + r0 + 2 * i, n1 = n0 + 1;
        float4 oA, oB;
        float v0, v1;
        upk2(acc[i][0], v0, v1); oA.x = v0; oB.x = v1;
        upk2(acc[i][1], v0, v1); oA.y = v0; oB.y = v1;
        upk2(acc[i][2], v0, v1); oA.z = v0; oB.z = v1;
        upk2(acc[i][3], v0, v1); oA.w = v0; oB.w = v1;
        if (n0 < NNODES) *(float4*)(g_P + (long long)n0 * Hdim + tx * 4) = oA;
        if (n1 < NNODES) *(float4*)(g_P + (long long)n1 * Hdim + tx * 4) = oB;
    }

    gemm_tile<128>(As, We1 + 128 * Hdim, (const float*)0, acc, tx, r0);
#pragma unroll
    for (int i = 0; i < 4; i++) {
        const int n0 = nb + r0 + 2 * i, n1 = n0 + 1;
        float4 oA, oB;
        float v0, v1;
        upk2(acc[i][0], v0, v1); oA.x = v0; oB.x = v1;
        upk2(acc[i][1], v0, v1); oA.y = v0; oB.y = v1;
        upk2(acc[i][2], v0, v1); oA.z = v0; oB.z = v1;
        upk2(acc[i][3], v0, v1); oA.w = v0; oB.w = v1;
        if (n0 < NNODES) *(float4*)(g_Q + (long long)n0 * Hdim + tx * 4) = oA;
        if (n1 < NNODES) *(float4*)(g_Q + (long long)n1 * Hdim + tx * 4) = oB;
    }
}

// ---------- edge kernel: single smem buffer, 4 CTAs/SM ----------
__global__ void __launch_bounds__(256, 4) edge_kernel(
    const float* __restrict__ x, const void* __restrict__ ei,
    const float* __restrict__ We1,
    const float* __restrict__ We2, const float* __restrict__ be2,
    const float* __restrict__ Wc1, const float* __restrict__ bc1,
    const float* __restrict__ Wc2,
    float* __restrict__ out_x) {
    extern __shared__ float sm[];
    float* As = sm;                      // 128 * LDA (m1, then m_ij)
    float* nd = As + 128 * LDA;          // 3 * TILE (normalized coord diffs)
    float* d2s = nd + 3 * TILE;          // TILE (radial)
    int*  rowi = (int*)(d2s + TILE);     // TILE
    int*  coli = rowi + TILE;            // TILE

    const int tid = threadIdx.x;
    const int tx = tid & 31, ty = tid >> 5;
    const int r0 = ty * 8;
    const int eb = blockIdx.x * TILE;
    const int is64 = g_is64;

    // 1) indices + coord geometry
    if (tid < TILE) {
        int e = tid;
        long long r, c;
        if (is64) {
            const long long* p = (const long long*)ei;
            r = p[eb + e]; c = p[NEDGES + eb + e];
        } else {
            const int* p = (const int*)ei;
            r = p[eb + e]; c = p[NEDGES + eb + e];
        }
        rowi[e] = (int)r; coli[e] = (int)c;
        float dx = __ldg(x + r * 3 + 0) - __ldg(x + c * 3 + 0);
        float dy = __ldg(x + r * 3 + 1) - __ldg(x + c * 3 + 1);
        float dz = __ldg(x + r * 3 + 2) - __ldg(x + c * 3 + 2);
        float d2 = dx * dx + dy * dy + dz * dz;
        float dist = sqrtf(d2);
        d2s[e] = d2;
        float inv = 1.0f / (dist + 1e-8f);
        nd[0 * TILE + e] = dx * inv;
        nd[1 * TILE + e] = dy * inv;
        nd[2 * TILE + e] = dz * inv;
    }
    __syncthreads();

    // 2) m1 = silu(P[row] + Q[col] + d2 * We1[256]) — layer-1 GEMM eliminated
    {
        const int d0 = tx * 4;
        float4 w1c = __ldg((const float4*)(We1 + 256 * Hdim + d0));
        for (int e = ty; e < TILE; e += 8) {
            const long long rr = rowi[e], cc = coli[e];
            float4 p = __ldg((const float4*)(g_P + rr * Hdim + d0));
            float4 q = __ldg((const float4*)(g_Q + cc * Hdim + d0));
            const float d2 = d2s[e];
            As[(d0 + 0) * LDA + e] = silu_f(fmaf(d2, w1c.x, p.x + q.x));
            As[(d0 + 1) * LDA + e] = silu_f(fmaf(d2, w1c.y, p.y + q.y));
            As[(d0 + 2) * LDA + e] = silu_f(fmaf(d2, w1c.z, p.z + q.z));
            As[(d0 + 3) * LDA + e] = silu_f(fmaf(d2, w1c.w, p.w + q.w));
        }
    }
    __syncthreads();

    unsigned long long acc[4][4];

    // 3) m_ij = silu(m1 @ We2 + be2); scatter to m_i; stash back into As
    gemm_tile<128>(As, We2, be2, acc, tx, r0);
#pragma unroll
    for (int i = 0; i < 4; i++) {
        float m0[4], m1v[4];
#pragma unroll
        for (int j = 0; j < 4; j++) {
            float v0, v1; upk2(acc[i][j], v0, v1);
            m0[j] = silu_f(v0); m1v[j] = silu_f(v1);
            acc[i][j] = pk2(m0[j], m1v[j]);
        }
        const int e0 = r0 + 2 * i, e1 = e0 + 1;
        red_add_v4(g_mi + (long long)rowi[e0] * Hdim + tx * 4, m0[0], m0[1], m0[2], m0[3]);
        red_add_v4(g_mi + (long long)rowi[e1] * Hdim + tx * 4, m1v[0], m1v[1], m1v[2], m1v[3]);
    }
    __syncthreads();  // all warps done reading m1 from As
#pragma unroll
    for (int i = 0; i < 4; i++)
#pragma unroll
        for (int j = 0; j < 4; j++)
            *(unsigned long long*)(As + (tx * 4 + j) * LDA + r0 + 2 * i) = acc[i][j];
    __syncthreads();  // m_ij stash visible

    // 4) c1 = silu(m_ij @ Wc1 + bc1); s = tanh(c1 . Wc2) * 0.1; force scatter
    gemm_tile<128>(As, Wc1, bc1, acc, tx, r0);
    float4 wc = __ldg((const float4*)(Wc2 + tx * 4));
    float par[8];
#pragma unroll
    for (int i = 0; i < 4; i++) {
        float p0 = 0.0f, p1 = 0.0f;
        {
            float v0, v1; upk2(acc[i][0], v0, v1);
            p0 += silu_f(v0) * wc.x; p1 += silu_f(v1) * wc.x;
        }
        {
            float v0, v1; upk2(acc[i][1], v0, v1);
            p0 += silu_f(v0) * wc.y; p1 += silu_f(v1) * wc.y;
        }
        {
            float v0, v1; upk2(acc[i][2], v0, v1);
            p0 += silu_f(v0) * wc.z; p1 += silu_f(v1) * wc.z;
        }
        {
            float v0, v1; upk2(acc[i][3], v0, v1);
            p0 += silu_f(v0) * wc.w; p1 += silu_f(v1) * wc.w;
        }
        par[2 * i] = p0; par[2 * i + 1] = p1;
    }
#pragma unroll
    for (int i = 0; i < 8; i++) {
#pragma unroll
        for (int off = 16; off > 0; off >>= 1)
            par[i] += __shfl_xor_sync(0xffffffffu, par[i], off);
    }
    if (tx == 0) {
#pragma unroll
        for (int i = 0; i < 8; i++) {
            const int e = r0 + i;
            const float s = tanhf(par[i]) * 0.1f;
            float* px = out_x + (long long)rowi[e] * 3;
            atomicAdd(px + 0, nd[0 * TILE + e] * s);
            atomicAdd(px + 1, nd[1 * TILE + e] * s);
            atomicAdd(px + 2, nd[2 * TILE + e] * s);
        }
    }
}

// ---------- node kernel: single smem buffer (B overwrites rows 0..127 of As) ----------
__global__ void __launch_bounds__(256, 3) node_kernel(
    const float* __restrict__ h,
    const float* __restrict__ Wn1, const float* __restrict__ bn1,
    const float* __restrict__ Wn2, const float* __restrict__ bn2,
    const float* __restrict__ lng, const float* __restrict__ lnb,
    float* __restrict__ out_h) {
    extern __shared__ float sm[];
    float* As = sm;  // 256 * LDA (node_input; rows 0..127 reused for B)

    const int tid = threadIdx.x;
    const int tx = tid & 31, ty = tid >> 5;
    const int r0 = ty * 8;
    const int nb = blockIdx.x * TILE;

    for (int e = ty; e < TILE; e += 8) {
        const int node = nb + e;
        const int d0 = tx * 4;
        if (node < NNODES) {
            float4 hv = __ldg((const float4*)(h + (long long)node * Hdim + d0));
            As[(d0 + 0) * LDA + e] = hv.x;
            As[(d0 + 1) * LDA + e] = hv.y;
            As[(d0 + 2) * LDA + e] = hv.z;
            As[(d0 + 3) * LDA + e] = hv.w;
            float4 mv = *(const float4*)(g_mi + (long long)node * Hdim + d0);
            As[(Hdim + d0 + 0) * LDA + e] = mv.x;
            As[(Hdim + d0 + 1) * LDA + e] = mv.y;
            As[(Hdim + d0 + 2) * LDA + e] = mv.z;
            As[(Hdim + d0 + 3) * LDA + e] = mv.w;
        } else {
#pragma unroll
            for (int q = 0; q < 4; q++) {
                As[(d0 + q) * LDA + e] = 0.0f;
                As[(Hdim + d0 + q) * LDA + e] = 0.0f;
            }
        }
    }
    __syncthreads();

    unsigned long long acc[4][4];
    gemm_tile<256>(As, Wn1, bn1, acc, tx, r0);
#pragma unroll
    for (int i = 0; i < 4; i++)
#pragma unroll
        for (int j = 0; j < 4; j++) {
            float v0, v1; upk2(acc[i][j], v0, v1);
            acc[i][j] = pk2(silu_f(v0), silu_f(v1));
        }
    __syncthreads();  // done reading node_input
#pragma unroll
    for (int i = 0; i < 4; i++)
#pragma unroll
        for (int j = 0; j < 4; j++)
            *(unsigned long long*)(As + (tx * 4 + j) * LDA + r0 + 2 * i) = acc[i][j];
    __syncthreads();

    gemm_tile<128>(As, Wn2, bn2, acc, tx, r0);

    float v[8][4];
#pragma unroll
    for (int i = 0; i < 4; i++) {
        const int n0 = nb + r0 + 2 * i, n1 = n0 + 1;
        float4 hA = make_float4(0.f, 0.f, 0.f, 0.f);
        float4 hB = make_float4(0.f, 0.f, 0.f, 0.f);
        if (n0 < NNODES) hA = __ldg((const float4*)(h + (long long)n0 * Hdim + tx * 4));
        if (n1 < NNODES) hB = __ldg((const float4*)(h + (long long)n1 * Hdim + tx * 4));
        float v0, v1;
        upk2(acc[i][0], v0, v1); v[2 * i][0] = v0 + hA.x; v[2 * i + 1][0] = v1 + hB.x;
        upk2(acc[i][1], v0, v1); v[2 * i][1] = v0 + hA.y; v[2 * i + 1][1] = v1 + hB.y;
        upk2(acc[i][2], v0, v1); v[2 * i][2] = v0 + hA.z; v[2 * i + 1][2] = v1 + hB.z;
        upk2(acc[i][3], v0, v1); v[2 * i][3] = v0 + hA.w; v[2 * i + 1][3] = v1 + hB.w;
    }

    float4 g4 = __ldg((const float4*)(lng + tx * 4));
    float4 b4 = __ldg((const float4*)(lnb + tx * 4));
#pragma unroll
    for (int rr = 0; rr < 8; rr++) {
        float s = v[rr][0] + v[rr][1] + v[rr][2] + v[rr][3];
        float q = v[rr][0] * v[rr][0] + v[rr][1] * v[rr][1] +
                  v[rr][2] * v[rr][2] + v[rr][3] * v[rr][3];
#pragma unroll
        for (int off = 16; off > 0; off >>= 1) {
            s += __shfl_xor_sync(0xffffffffu, s, off);
            q += __shfl_xor_sync(0xffffffffu, q, off);
        }
        const float mu = s * (1.0f / 128.0f);
        const float var = q * (1.0f / 128.0f) - mu * mu;
        const float rstd = rsqrtf(var + 1e-5f);
        const int node = nb + r0 + rr;
        if (node < NNODES) {
            float4 o;
            o.x = (v[rr][0] - mu) * rstd * g4.x + b4.x;
            o.y = (v[rr][1] - mu) * rstd * g4.y + b4.y;
            o.z = (v[rr][2] - mu) * rstd * g4.z + b4.z;
            o.w = (v[rr][3] - mu) * rstd * g4.w + b4.w;
            *(float4*)(out_h + (long long)node * Hdim + tx * 4) = o;
        }
    }
}

// ---------- launch ----------
extern "C" void kernel_launch(void* const* d_in, const int* in_sizes, int n_in,
                              void* d_out, int out_size) {
    const float* h   = (const float*)d_in[0];
    const float* x   = (const float*)d_in[1];
    const void*  ei  = d_in[2];
    const float* We1 = (const float*)d_in[3];
    const float* be1 = (const float*)d_in[4];
    const float* We2 = (const float*)d_in[5];
    const float* be2 = (const float*)d_in[6];
    const float* Wc1 = (const float*)d_in[7];
    const float* bc1 = (const float*)d_in[8];
    const float* Wc2 = (const float*)d_in[9];
    const float* Wn1 = (const float*)d_in[10];
    const float* bn1 = (const float*)d_in[11];
    const float* Wn2 = (const float*)d_in[12];
    const float* bn2 = (const float*)d_in[13];
    const float* lng = (const float*)d_in[14];
    const float* lnb = (const float*)d_in[15];

    float* out_h = (float*)d_out;
    float* out_x = out_h + (long long)NNODES * Hdim;

    const int SMEM_PREP = (128 * LDA) * 4;
    const int SMEM_EDGE = (128 * LDA + 3 * TILE + TILE + 2 * TILE) * 4;
    const int SMEM_NODE = (256 * LDA) * 4;

    cudaFuncSetAttribute(prep_kernel, cudaFuncAttributeMaxDynamicSharedMemorySize, SMEM_PREP);
    cudaFuncSetAttribute(edge_kernel, cudaFuncAttributeMaxDynamicSharedMemorySize, SMEM_EDGE);
    cudaFuncSetAttribute(node_kernel, cudaFuncAttributeMaxDynamicSharedMemorySize, SMEM_NODE);

    detect_kernel<<<1, 32>>>((const int*)ei);
    init_kernel<<<((long long)NNODES * Hdim + 255) / 256, 256>>>(x, out_x);
    prep_kernel<<<(NNODES + TILE - 1) / TILE, 256, SMEM_PREP>>>(h, We1, be1);
    edge_kernel<<<NEDGES / TILE, 256, SMEM_EDGE>>>(x, ei, We1, We2, be2,
                                                   Wc1, bc1, Wc2, out_x);
    node_kernel<<<(NNODES + TILE - 1) / TILE, 256, SMEM_NODE>>>(h, Wn1, bn1, Wn2, bn2,
                                                                lng, lnb, out_h);
}

// round 8
// speedup vs baseline: 1.0078x; 1.0078x over previous
#include <cuda_runtime.h>

#define Hdim 128
#define NNODES 50000
#define NEDGES 800000
#define TILE 64        // prep/node tile
#define LDA 68         // prep/node feature-major stride
#define ETILE 128      // edge tile (edges per CTA)
#define LDE 132        // edge feature-major stride (mult of 4 => 16B-aligned)

__device__ int   g_is64;
__device__ float g_mi[(long long)NNODES * Hdim];  // segment-summed m_i scratch
__device__ float g_P [(long long)NNODES * Hdim];  // h @ We1[0:128]   + be1
__device__ float g_Q [(long long)NNODES * Hdim];  // h @ We1[128:256]

// ---------- f32x2 helpers ----------
__device__ __forceinline__ unsigned long long pk2(float lo, float hi) {
    unsigned long long r;
    asm("mov.b64 %0, {%1,%2};" : "=l"(r) : "f"(lo), "f"(hi));
    return r;
}
__device__ __forceinline__ void upk2(unsigned long long v, float& lo, float& hi) {
    asm("mov.b64 {%0,%1}, %2;" : "=f"(lo), "=f"(hi) : "l"(v));
}
#define FMA2(d, a, b) asm("fma.rn.f32x2 %0, %1, %2, %0;" : "+l"(d) : "l"(a), "l"(b))

__device__ __forceinline__ void red_add_v4(float* p, float a, float b, float c, float d) {
    asm volatile("red.global.add.v4.f32 [%0], {%1,%2,%3,%4};"
                 :: "l"(p), "f"(a), "f"(b), "f"(c), "f"(d) : "memory");
}

__device__ __forceinline__ float silu_f(float v) { return v / (1.0f + __expf(-v)); }

// ---------- prep/node GEMM tile (R5-proven): 8 rows x 4 cols per thread ----------
template <int K>
__device__ __forceinline__ void gemm_tile(const float* __restrict__ As,
                                          const float* __restrict__ W,
                                          const float* __restrict__ bias,
                                          unsigned long long acc[4][4],
                                          int tx, int r0) {
    float4 b4 = bias ? __ldg((const float4*)(bias + tx * 4))
                     : make_float4(0.f, 0.f, 0.f, 0.f);
#pragma unroll
    for (int i = 0; i < 4; i++) {
        acc[i][0] = pk2(b4.x, b4.x);
        acc[i][1] = pk2(b4.y, b4.y);
        acc[i][2] = pk2(b4.z, b4.z);
        acc[i][3] = pk2(b4.w, b4.w);
    }
#pragma unroll 4
    for (int k = 0; k < K; k++) {
        float4 w = __ldg((const float4*)(W + (long long)k * Hdim + tx * 4));
        unsigned long long w0 = pk2(w.x, w.x);
        unsigned long long w1 = pk2(w.y, w.y);
        unsigned long long w2 = pk2(w.z, w.z);
        unsigned long long w3 = pk2(w.w, w.w);
        const float* ak = As + k * LDA + r0;
        ulonglong2 aP = *(const ulonglong2*)(ak);
        ulonglong2 aQ = *(const ulonglong2*)(ak + 4);
        unsigned long long a2[4] = {aP.x, aP.y, aQ.x, aQ.y};
#pragma unroll
        for (int i = 0; i < 4; i++) {
            FMA2(acc[i][0], a2[i], w0);
            FMA2(acc[i][1], a2[i], w1);
            FMA2(acc[i][2], a2[i], w2);
            FMA2(acc[i][3], a2[i], w3);
        }
    }
}

// ---------- edge GEMM tile: 16 rows x 4 cols per thread ----------
// Per warp-k: 1 LDG.128 (W, L1-hit) + 4 LDS.128 (A row pairs, broadcast) + 32 FFMA2.
// W traffic per MAC halved vs the 8-row tile => FMA-pipe-dominant.
template <int K>
__device__ __forceinline__ void gemm_tile16(const float* __restrict__ As,
                                            const float* __restrict__ W,
                                            const float* __restrict__ bias,
                                            unsigned long long acc[8][4],
                                            int tx, int r0) {
    float4 b4 = __ldg((const float4*)(bias + tx * 4));
#pragma unroll
    for (int i = 0; i < 8; i++) {
        acc[i][0] = pk2(b4.x, b4.x);
        acc[i][1] = pk2(b4.y, b4.y);
        acc[i][2] = pk2(b4.z, b4.z);
        acc[i][3] = pk2(b4.w, b4.w);
    }
#pragma unroll 2
    for (int k = 0; k < K; k++) {
        float4 w = __ldg((const float4*)(W + (long long)k * Hdim + tx * 4));
        unsigned long long w0 = pk2(w.x, w.x);
        unsigned long long w1 = pk2(w.y, w.y);
        unsigned long long w2 = pk2(w.z, w.z);
        unsigned long long w3 = pk2(w.w, w.w);
        const float* ak = As + k * LDE + r0;
        ulonglong2 aP = *(const ulonglong2*)(ak);
        ulonglong2 aQ = *(const ulonglong2*)(ak + 4);
        ulonglong2 aR = *(const ulonglong2*)(ak + 8);
        ulonglong2 aS = *(const ulonglong2*)(ak + 12);
        unsigned long long a2[8] = {aP.x, aP.y, aQ.x, aQ.y, aR.x, aR.y, aS.x, aS.y};
#pragma unroll
        for (int i = 0; i < 8; i++) {
            FMA2(acc[i][0], a2[i], w0);
            FMA2(acc[i][1], a2[i], w1);
            FMA2(acc[i][2], a2[i], w2);
            FMA2(acc[i][3], a2[i], w3);
        }
    }
}

// ---------- index dtype detection (int32 vs int64) ----------
__global__ void detect_kernel(const int* ei32) {
    if (blockIdx.x == 0 && threadIdx.x == 0) {
        int f = 1;
        for (int i = 0; i < 1024; i++) {
            if (ei32[2 * i + 1] != 0) { f = 0; break; }
        }
        g_is64 = f;
    }
}

// ---------- init: zero m_i scratch, seed out_x = x ----------
__global__ void init_kernel(const float* __restrict__ x, float* __restrict__ out_x) {
    long long i = (long long)blockIdx.x * blockDim.x + threadIdx.x;
    if (i < (long long)NNODES * Hdim) g_mi[i] = 0.0f;
    if (i < (long long)NNODES * 3)    out_x[i] = x[i];
}

// ---------- prep: P = h @ We1[0:128] + be1 ; Q = h @ We1[128:256] ----------
__global__ void __launch_bounds__(256) prep_kernel(
    const float* __restrict__ h,
    const float* __restrict__ We1, const float* __restrict__ be1) {
    extern __shared__ float sm[];
    float* As = sm;  // 128 * LDA

    const int tid = threadIdx.x;
    const int tx = tid & 31, ty = tid >> 5;
    const int r0 = ty * 8;
    const int nb = blockIdx.x * TILE;

    for (int e = ty; e < TILE; e += 8) {
        const int node = nb + e;
        const int d0 = tx * 4;
        float4 hv = make_float4(0.f, 0.f, 0.f, 0.f);
        if (node < NNODES) hv = __ldg((const float4*)(h + (long long)node * Hdim + d0));
        As[(d0 + 0) * LDA + e] = hv.x;
        As[(d0 + 1) * LDA + e] = hv.y;
        As[(d0 + 2) * LDA + e] = hv.z;
        As[(d0 + 3) * LDA + e] = hv.w;
    }
    __syncthreads();

    unsigned long long acc[4][4];

    gemm_tile<128>(As, We1, be1, acc, tx, r0);
#pragma unroll
    for (int i = 0; i < 4; i++) {
        const int n0 = nb + r0 + 2 * i, n1 = n0 + 1;
        float4 oA, oB;
        float v0, v1;
        upk2(acc[i][0], v0, v1); oA.x = v0; oB.x = v1;
        upk2(acc[i][1], v0, v1); oA.y = v0; oB.y = v1;
        upk2(acc[i][2], v0, v1); oA.z = v0; oB.z = v1;
        upk2(acc[i][3], v0, v1); oA.w = v0; oB.w = v1;
        if (n0 < NNODES) *(float4*)(g_P + (long long)n0 * Hdim + tx * 4) = oA;
        if (n1 < NNODES) *(float4*)(g_P + (long long)n1 * Hdim + tx * 4) = oB;
    }

    gemm_tile<128>(As, We1 + 128 * Hdim, (const float*)0, acc, tx, r0);
#pragma unroll
    for (int i = 0; i < 4; i++) {
        const int n0 = nb + r0 + 2 * i, n1 = n0 + 1;
        float4 oA, oB;
        float v0, v1;
        upk2(acc[i][0], v0, v1); oA.x = v0; oB.x = v1;
        upk2(acc[i][1], v0, v1); oA.y = v0; oB.y = v1;
        upk2(acc[i][2], v0, v1); oA.z = v0; oB.z = v1;
        upk2(acc[i][3], v0, v1); oA.w = v0; oB.w = v1;
        if (n0 < NNODES) *(float4*)(g_Q + (long long)n0 * Hdim + tx * 4) = oA;
        if (n1 < NNODES) *(float4*)(g_Q + (long long)n1 * Hdim + tx * 4) = oB;
    }
}

// ---------- edge kernel: 128-edge tile, 16 rows/warp, single smem buffer ----------
__global__ void __launch_bounds__(256) edge_kernel(
    const float* __restrict__ x, const void* __restrict__ ei,
    const float* __restrict__ We1,
    const float* __restrict__ We2, const float* __restrict__ be2,
    const float* __restrict__ Wc1, const float* __restrict__ bc1,
    const float* __restrict__ Wc2,
    float* __restrict__ out_x) {
    extern __shared__ float sm[];
    float* As = sm;                      // 128 * LDE (m1, then m_ij)
    float* nd = As + 128 * LDE;          // 3 * ETILE (normalized coord diffs)
    float* d2s = nd + 3 * ETILE;         // ETILE (radial)
    int*  rowi = (int*)(d2s + ETILE);    // ETILE
    int*  coli = rowi + ETILE;           // ETILE

    const int tid = threadIdx.x;
    const int tx = tid & 31, ty = tid >> 5;
    const int r0 = ty * 16;
    const int eb = blockIdx.x * ETILE;
    const int is64 = g_is64;

    // 1) indices + coord geometry (128 edges, 128 threads)
    if (tid < ETILE) {
        int e = tid;
        long long r, c;
        if (is64) {
            const long long* p = (const long long*)ei;
            r = p[eb + e]; c = p[NEDGES + eb + e];
        } else {
            const int* p = (const int*)ei;
            r = p[eb + e]; c = p[NEDGES + eb + e];
        }
        rowi[e] = (int)r; coli[e] = (int)c;
        float dx = __ldg(x + r * 3 + 0) - __ldg(x + c * 3 + 0);
        float dy = __ldg(x + r * 3 + 1) - __ldg(x + c * 3 + 1);
        float dz = __ldg(x + r * 3 + 2) - __ldg(x + c * 3 + 2);
        float d2 = dx * dx + dy * dy + dz * dz;
        float dist = sqrtf(d2);
        d2s[e] = d2;
        float inv = 1.0f / (dist + 1e-8f);
        nd[0 * ETILE + e] = dx * inv;
        nd[1 * ETILE + e] = dy * inv;
        nd[2 * ETILE + e] = dz * inv;
    }
    __syncthreads();

    // 2) m1 = silu(P[row] + Q[col] + d2 * We1[256]) — feature-major into As
    {
        const int d0 = tx * 4;
        float4 w1c = __ldg((const float4*)(We1 + 256 * Hdim + d0));
        for (int e = ty; e < ETILE; e += 8) {
            const long long rr = rowi[e], cc = coli[e];
            float4 p = __ldg((const float4*)(g_P + rr * Hdim + d0));
            float4 q = __ldg((const float4*)(g_Q + cc * Hdim + d0));
            const float d2 = d2s[e];
            As[(d0 + 0) * LDE + e] = silu_f(fmaf(d2, w1c.x, p.x + q.x));
            As[(d0 + 1) * LDE + e] = silu_f(fmaf(d2, w1c.y, p.y + q.y));
            As[(d0 + 2) * LDE + e] = silu_f(fmaf(d2, w1c.z, p.z + q.z));
            As[(d0 + 3) * LDE + e] = silu_f(fmaf(d2, w1c.w, p.w + q.w));
        }
    }
    __syncthreads();

    unsigned long long acc[8][4];

    // 3) m_ij = silu(m1 @ We2 + be2); scatter to m_i; stash back into As
    gemm_tile16<128>(As, We2, be2, acc, tx, r0);
#pragma unroll
    for (int i = 0; i < 8; i++) {
        float m0[4], m1v[4];
#pragma unroll
        for (int j = 0; j < 4; j++) {
            float v0, v1; upk2(acc[i][j], v0, v1);
            m0[j] = silu_f(v0); m1v[j] = silu_f(v1);
            acc[i][j] = pk2(m0[j], m1v[j]);
        }
        const int e0 = r0 + 2 * i, e1 = e0 + 1;
        red_add_v4(g_mi + (long long)rowi[e0] * Hdim + tx * 4, m0[0], m0[1], m0[2], m0[3]);
        red_add_v4(g_mi + (long long)rowi[e1] * Hdim + tx * 4, m1v[0], m1v[1], m1v[2], m1v[3]);
    }
    __syncthreads();  // all warps done reading m1 from As
#pragma unroll
    for (int i = 0; i < 8; i++)
#pragma unroll
        for (int j = 0; j < 4; j++)
            *(unsigned long long*)(As + (tx * 4 + j) * LDE + r0 + 2 * i) = acc[i][j];
    __syncthreads();  // m_ij stash visible

    // 4) c1 = silu(m_ij @ Wc1 + bc1); s = tanh(c1 . Wc2) * 0.1; force scatter
    gemm_tile16<128>(As, Wc1, bc1, acc, tx, r0);
    float4 wc = __ldg((const float4*)(Wc2 + tx * 4));
    float par[16];
#pragma unroll
    for (int i = 0; i < 8; i++) {
        float p0 = 0.0f, p1 = 0.0f;
        float v0, v1;
        upk2(acc[i][0], v0, v1); p0 = fmaf(silu_f(v0), wc.x, p0); p1 = fmaf(silu_f(v1), wc.x, p1);
        upk2(acc[i][1], v0, v1); p0 = fmaf(silu_f(v0), wc.y, p0); p1 = fmaf(silu_f(v1), wc.y, p1);
        upk2(acc[i][2], v0, v1); p0 = fmaf(silu_f(v0), wc.z, p0); p1 = fmaf(silu_f(v1), wc.z, p1);
        upk2(acc[i][3], v0, v1); p0 = fmaf(silu_f(v0), wc.w, p0); p1 = fmaf(silu_f(v1), wc.w, p1);
        par[2 * i] = p0; par[2 * i + 1] = p1;
    }
#pragma unroll
    for (int i = 0; i < 16; i++) {
#pragma unroll
        for (int off = 16; off > 0; off >>= 1)
            par[i] += __shfl_xor_sync(0xffffffffu, par[i], off);
    }
    if (tx == 0) {
#pragma unroll
        for (int i = 0; i < 16; i++) {
            const int e = r0 + i;
            const float s = tanhf(par[i]) * 0.1f;
            float* px = out_x + (long long)rowi[e] * 3;
            atomicAdd(px + 0, nd[0 * ETILE + e] * s);
            atomicAdd(px + 1, nd[1 * ETILE + e] * s);
            atomicAdd(px + 2, nd[2 * ETILE + e] * s);
        }
    }
}

// ---------- node kernel: node MLP + residual + LayerNorm (R5-proven) ----------
__global__ void __launch_bounds__(256, 2) node_kernel(
    const float* __restrict__ h,
    const float* __restrict__ Wn1, const float* __restrict__ bn1,
    const float* __restrict__ Wn2, const float* __restrict__ bn2,
    const float* __restrict__ lng, const float* __restrict__ lnb,
    float* __restrict__ out_h) {
    extern __shared__ float sm[];
    float* As = sm;               // 256 * LDA
    float* Bs = As + 256 * LDA;   // 128 * LDA

    const int tid = threadIdx.x;
    const int tx = tid & 31, ty = tid >> 5;
    const int r0 = ty * 8;
    const int nb = blockIdx.x * TILE;

    for (int e = ty; e < TILE; e += 8) {
        const int node = nb + e;
        const int d0 = tx * 4;
        if (node < NNODES) {
            float4 hv = __ldg((const float4*)(h + (long long)node * Hdim + d0));
            As[(d0 + 0) * LDA + e] = hv.x;
            As[(d0 + 1) * LDA + e] = hv.y;
            As[(d0 + 2) * LDA + e] = hv.z;
            As[(d0 + 3) * LDA + e] = hv.w;
            float4 mv = *(const float4*)(g_mi + (long long)node * Hdim + d0);
            As[(Hdim + d0 + 0) * LDA + e] = mv.x;
            As[(Hdim + d0 + 1) * LDA + e] = mv.y;
            As[(Hdim + d0 + 2) * LDA + e] = mv.z;
            As[(Hdim + d0 + 3) * LDA + e] = mv.w;
        } else {
#pragma unroll
            for (int q = 0; q < 4; q++) {
                As[(d0 + q) * LDA + e] = 0.0f;
                As[(Hdim + d0 + q) * LDA + e] = 0.0f;
            }
        }
    }
    __syncthreads();

    unsigned long long acc[4][4];
    gemm_tile<256>(As, Wn1, bn1, acc, tx, r0);
#pragma unroll
    for (int i = 0; i < 4; i++) {
#pragma unroll
        for (int j = 0; j < 4; j++) {
            float v0, v1; upk2(acc[i][j], v0, v1);
            *(unsigned long long*)(Bs + (tx * 4 + j) * LDA + r0 + 2 * i) =
                pk2(silu_f(v0), silu_f(v1));
        }
    }
    __syncthreads();

    gemm_tile<128>(Bs, Wn2, bn2, acc, tx, r0);

    float v[8][4];
#pragma unroll
    for (int i = 0; i < 4; i++) {
        const int n0 = nb + r0 + 2 * i, n1 = n0 + 1;
        float4 hA = make_float4(0.f, 0.f, 0.f, 0.f);
        float4 hB = make_float4(0.f, 0.f, 0.f, 0.f);
        if (n0 < NNODES) hA = __ldg((const float4*)(h + (long long)n0 * Hdim + tx * 4));
        if (n1 < NNODES) hB = __ldg((const float4*)(h + (long long)n1 * Hdim + tx * 4));
        float v0, v1;
        upk2(acc[i][0], v0, v1); v[2 * i][0] = v0 + hA.x; v[2 * i + 1][0] = v1 + hB.x;
        upk2(acc[i][1], v0, v1); v[2 * i][1] = v0 + hA.y; v[2 * i + 1][1] = v1 + hB.y;
        upk2(acc[i][2], v0, v1); v[2 * i][2] = v0 + hA.z; v[2 * i + 1][2] = v1 + hB.z;
        upk2(acc[i][3], v0, v1); v[2 * i][3] = v0 + hA.w; v[2 * i + 1][3] = v1 + hB.w;
    }

    float4 g4 = __ldg((const float4*)(lng + tx * 4));
    float4 b4 = __ldg((const float4*)(lnb + tx * 4));
#pragma unroll
    for (int rr = 0; rr < 8; rr++) {
        float s = v[rr][0] + v[rr][1] + v[rr][2] + v[rr][3];
        float q = v[rr][0] * v[rr][0] + v[rr][1] * v[rr][1] +
                  v[rr][2] * v[rr][2] + v[rr][3] * v[rr][3];
#pragma unroll
        for (int off = 16; off > 0; off >>= 1) {
            s += __shfl_xor_sync(0xffffffffu, s, off);
            q += __shfl_xor_sync(0xffffffffu, q, off);
        }
        const float mu = s * (1.0f / 128.0f);
        const float var = q * (1.0f / 128.0f) - mu * mu;
        const float rstd = rsqrtf(var + 1e-5f);
        const int node = nb + r0 + rr;
        if (node < NNODES) {
            float4 o;
            o.x = (v[rr][0] - mu) * rstd * g4.x + b4.x;
            o.y = (v[rr][1] - mu) * rstd * g4.y + b4.y;
            o.z = (v[rr][2] - mu) * rstd * g4.z + b4.z;
            o.w = (v[rr][3] - mu) * rstd * g4.w + b4.w;
            *(float4*)(out_h + (long long)node * Hdim + tx * 4) = o;
        }
    }
}

// ---------- launch ----------
extern "C" void kernel_launch(void* const* d_in, const int* in_sizes, int n_in,
                              void* d_out, int out_size) {
    const float* h   = (const float*)d_in[0];
    const float* x   = (const float*)d_in[1];
    const void*  ei  = d_in[2];
    const float* We1 = (const float*)d_in[3];
    const float* be1 = (const float*)d_in[4];
    const float* We2 = (const float*)d_in[5];
    const float* be2 = (const float*)d_in[6];
    const float* Wc1 = (const float*)d_in[7];
    const float* bc1 = (const float*)d_in[8];
    const float* Wc2 = (const float*)d_in[9];
    const float* Wn1 = (const float*)d_in[10];
    const float* bn1 = (const float*)d_in[11];
    const float* Wn2 = (const float*)d_in[12];
    const float* bn2 = (const float*)d_in[13];
    const float* lng = (const float*)d_in[14];
    const float* lnb = (const float*)d_in[15];

    float* out_h = (float*)d_out;
    float* out_x = out_h + (long long)NNODES * Hdim;

    const int SMEM_PREP = (128 * LDA) * 4;
    const int SMEM_EDGE = (128 * LDE + 3 * ETILE + ETILE + 2 * ETILE) * 4;
    const int SMEM_NODE = (256 * LDA + 128 * LDA) * 4;

    cudaFuncSetAttribute(prep_kernel, cudaFuncAttributeMaxDynamicSharedMemorySize, SMEM_PREP);
    cudaFuncSetAttribute(edge_kernel, cudaFuncAttributeMaxDynamicSharedMemorySize, SMEM_EDGE);
    cudaFuncSetAttribute(node_kernel, cudaFuncAttributeMaxDynamicSharedMemorySize, SMEM_NODE);

    detect_kernel<<<1, 32>>>((const int*)ei);
    init_kernel<<<((long long)NNODES * Hdim + 255) / 256, 256>>>(x, out_x);
    prep_kernel<<<(NNODES + TILE - 1) / TILE, 256, SMEM_PREP>>>(h, We1, be1);
    edge_kernel<<<NEDGES / ETILE, 256, SMEM_EDGE>>>(x, ei, We1, We2, be2,
                                                    Wc1, bc1, Wc2, out_x);
    node_kernel<<<(NNODES + TILE - 1) / TILE, 256, SMEM_NODE>>>(h, Wn1, bn1, Wn2, bn2,
                                                                lng, lnb, out_h);
}

// round 10
// speedup vs baseline: 1.1373x; 1.1285x over previous
#include <cuda_runtime.h>

#define Hdim 128
#define NNODES 50000
#define NEDGES 800000
#define TILE 64
#define LDA 68
// Within-row quad-XOR swizzle: element (f,e) lives at
//   f*LDA + ((e>>2) ^ ((f>>2)&15))*4 + (e&3)
// Physical offset stays in [0,63] (16 quads) => rows never overlap.
// Scalar feature-major stores go from 16-way to ~4-way bank conflicts;
// GEMM A-reads remain two warp-uniform 16B LDS.128 broadcasts.
#define SWZ(f, e) ((f) * LDA + ((((((e) >> 2)) ^ (((f) >> 2) & 15)) << 2) | ((e) & 3)))
#define BUF128 (128 * LDA)
#define BUF256 (256 * LDA)

__device__ int   g_is64;
__device__ float g_mi[(long long)NNODES * Hdim];  // segment-summed m_i scratch
__device__ float g_P [(long long)NNODES * Hdim];  // h @ We1[0:128]   + be1
__device__ float g_Q [(long long)NNODES * Hdim];  // h @ We1[128:256]

// ---------- f32x2 helpers ----------
__device__ __forceinline__ unsigned long long pk2(float lo, float hi) {
    unsigned long long r;
    asm("mov.b64 %0, {%1,%2};" : "=l"(r) : "f"(lo), "f"(hi));
    return r;
}
__device__ __forceinline__ void upk2(unsigned long long v, float& lo, float& hi) {
    asm("mov.b64 {%0,%1}, %2;" : "=f"(lo), "=f"(hi) : "l"(v));
}
#define FMA2(d, a, b) asm("fma.rn.f32x2 %0, %1, %2, %0;" : "+l"(d) : "l"(a), "l"(b))

__device__ __forceinline__ void red_add_v4(float* p, float a, float b, float c, float d) {
    asm volatile("red.global.add.v4.f32 [%0], {%1,%2,%3,%4};"
                 :: "l"(p), "f"(a), "f"(b), "f"(c), "f"(d) : "memory");
}

__device__ __forceinline__ float silu_f(float v) { return v / (1.0f + __expf(-v)); }

// ---------- GEMM tile: C[64 rows x 128 cols] = A[64 x K] * W[K x 128] (+ bias) ----------
// A feature-major (quad-XOR swizzled) in smem. Thread (tx,ty): rows r0..r0+7 as
// 4 packed pairs via 2 warp-uniform LDS.128 (quads (Q^s),(Q+1)^s), cols tx*4..+3.
template <int K>
__device__ __forceinline__ void gemm_tile(const float* __restrict__ As,
                                          const float* __restrict__ W,
                                          const float* __restrict__ bias,
                                          unsigned long long acc[4][4],
                                          int tx, int r0) {
    const int Q = r0 >> 2;  // even (r0 multiple of 8)
    float4 b4 = bias ? __ldg((const float4*)(bias + tx * 4))
                     : make_float4(0.f, 0.f, 0.f, 0.f);
#pragma unroll
    for (int i = 0; i < 4; i++) {
        acc[i][0] = pk2(b4.x, b4.x);
        acc[i][1] = pk2(b4.y, b4.y);
        acc[i][2] = pk2(b4.z, b4.z);
        acc[i][3] = pk2(b4.w, b4.w);
    }
#pragma unroll 4
    for (int k = 0; k < K; k++) {
        float4 w = __ldg((const float4*)(W + (long long)k * Hdim + tx * 4));
        unsigned long long w0 = pk2(w.x, w.x);
        unsigned long long w1 = pk2(w.y, w.y);
        unsigned long long w2 = pk2(w.z, w.z);
        unsigned long long w3 = pk2(w.w, w.w);
        const int s = (k >> 2) & 15;
        const float* bk = As + k * LDA;
        ulonglong2 aP = *(const ulonglong2*)(bk + ((Q ^ s) << 2));        // rows r0..r0+3
        ulonglong2 aQ = *(const ulonglong2*)(bk + (((Q + 1) ^ s) << 2));  // rows r0+4..r0+7
        unsigned long long a2[4] = {aP.x, aP.y, aQ.x, aQ.y};
#pragma unroll
        for (int i = 0; i < 4; i++) {
            FMA2(acc[i][0], a2[i], w0);
            FMA2(acc[i][1], a2[i], w1);
            FMA2(acc[i][2], a2[i], w2);
            FMA2(acc[i][3], a2[i], w3);
        }
    }
}

// ---------- index dtype detection (int32 vs int64) ----------
__global__ void detect_kernel(const int* ei32) {
    if (blockIdx.x == 0 && threadIdx.x == 0) {
        int f = 1;
        for (int i = 0; i < 1024; i++) {
            if (ei32[2 * i + 1] != 0) { f = 0; break; }
        }
        g_is64 = f;
    }
}

// ---------- init: zero m_i scratch, seed out_x = x ----------
__global__ void init_kernel(const float* __restrict__ x, float* __restrict__ out_x) {
    long long i = (long long)blockIdx.x * blockDim.x + threadIdx.x;
    if (i < (long long)NNODES * Hdim) g_mi[i] = 0.0f;
    if (i < (long long)NNODES * 3)    out_x[i] = x[i];
}

// ---------- prep: P = h @ We1[0:128] + be1 ; Q = h @ We1[128:256] ----------
__global__ void __launch_bounds__(256) prep_kernel(
    const float* __restrict__ h,
    const float* __restrict__ We1, const float* __restrict__ be1) {
    extern __shared__ float sm[];
    float* As = sm;  // BUF128

    const int tid = threadIdx.x;
    const int tx = tid & 31, ty = tid >> 5;
    const int r0 = ty * 8;
    const int nb = blockIdx.x * TILE;

    for (int e = ty; e < TILE; e += 8) {
        const int node = nb + e;
        const int d0 = tx * 4;
        float4 hv = make_float4(0.f, 0.f, 0.f, 0.f);
        if (node < NNODES) hv = __ldg((const float4*)(h + (long long)node * Hdim + d0));
        As[SWZ(d0 + 0, e)] = hv.x;
        As[SWZ(d0 + 1, e)] = hv.y;
        As[SWZ(d0 + 2, e)] = hv.z;
        As[SWZ(d0 + 3, e)] = hv.w;
    }
    __syncthreads();

    unsigned long long acc[4][4];

    gemm_tile<128>(As, We1, be1, acc, tx, r0);
#pragma unroll
    for (int i = 0; i < 4; i++) {
        const int n0 = nb + r0 + 2 * i, n1 = n0 + 1;
        float4 oA, oB;
        float v0, v1;
        upk2(acc[i][0], v0, v1); oA.x = v0; oB.x = v1;
        upk2(acc[i][1], v0, v1); oA.y = v0; oB.y = v1;
        upk2(acc[i][2], v0, v1); oA.z = v0; oB.z = v1;
        upk2(acc[i][3], v0, v1); oA.w = v0; oB.w = v1;
        if (n0 < NNODES) *(float4*)(g_P + (long long)n0 * Hdim + tx * 4) = oA;
        if (n1 < NNODES) *(float4*)(g_P + (long long)n1 * Hdim + tx * 4) = oB;
    }

    gemm_tile<128>(As, We1 + 128 * Hdim, (const float*)0, acc, tx, r0);
#pragma unroll
    for (int i = 0; i < 4; i++) {
        const int n0 = nb + r0 + 2 * i, n1 = n0 + 1;
        float4 oA, oB;
        float v0, v1;
        upk2(acc[i][0], v0, v1); oA.x = v0; oB.x = v1;
        upk2(acc[i][1], v0, v1); oA.y = v0; oB.y = v1;
        upk2(acc[i][2], v0, v1); oA.z = v0; oB.z = v1;
        upk2(acc[i][3], v0, v1); oA.w = v0; oB.w = v1;
        if (n0 < NNODES) *(float4*)(g_Q + (long long)n0 * Hdim + tx * 4) = oA;
        if (n1 < NNODES) *(float4*)(g_Q + (long long)n1 * Hdim + tx * 4) = oB;
    }
}

// ---------- edge kernel (R5 structure + quad-XOR swizzled smem) ----------
__global__ void __launch_bounds__(256, 3) edge_kernel(
    const float* __restrict__ x, const void* __restrict__ ei,
    const float* __restrict__ We1,
    const float* __restrict__ We2, const float* __restrict__ be2,
    const float* __restrict__ Wc1, const float* __restrict__ bc1,
    const float* __restrict__ Wc2,
    float* __restrict__ out_x) {
    extern __shared__ float sm[];
    float* As = sm;                      // BUF128 (m1)
    float* Bs = As + BUF128;             // BUF128 (m_ij)
    float* nd = Bs + BUF128;             // 3 * TILE
    float* d2s = nd + 3 * TILE;          // TILE
    int*  rowi = (int*)(d2s + TILE);     // TILE
    int*  coli = rowi + TILE;            // TILE

    const int tid = threadIdx.x;
    const int tx = tid & 31, ty = tid >> 5;
    const int r0 = ty * 8;
    const int eb = blockIdx.x * TILE;
    const int is64 = g_is64;

    // 1) indices + coord geometry
    if (tid < TILE) {
        int e = tid;
        long long r, c;
        if (is64) {
            const long long* p = (const long long*)ei;
            r = p[eb + e]; c = p[NEDGES + eb + e];
        } else {
            const int* p = (const int*)ei;
            r = p[eb + e]; c = p[NEDGES + eb + e];
        }
        rowi[e] = (int)r; coli[e] = (int)c;
        float dx = __ldg(x + r * 3 + 0) - __ldg(x + c * 3 + 0);
        float dy = __ldg(x + r * 3 + 1) - __ldg(x + c * 3 + 1);
        float dz = __ldg(x + r * 3 + 2) - __ldg(x + c * 3 + 2);
        float d2 = dx * dx + dy * dy + dz * dz;
        float dist = sqrtf(d2);
        d2s[e] = d2;
        float inv = 1.0f / (dist + 1e-8f);
        nd[0 * TILE + e] = dx * inv;
        nd[1 * TILE + e] = dy * inv;
        nd[2 * TILE + e] = dz * inv;
    }
    __syncthreads();

    // 2) m1 = silu(P[row] + Q[col] + d2 * We1[256])
    {
        const int d0 = tx * 4;
        float4 w1c = __ldg((const float4*)(We1 + 256 * Hdim + d0));
        for (int e = ty; e < TILE; e += 8) {
            const long long rr = rowi[e], cc = coli[e];
            float4 p = __ldg((const float4*)(g_P + rr * Hdim + d0));
            float4 q = __ldg((const float4*)(g_Q + cc * Hdim + d0));
            const float d2 = d2s[e];
            As[SWZ(d0 + 0, e)] = silu_f(fmaf(d2, w1c.x, p.x + q.x));
            As[SWZ(d0 + 1, e)] = silu_f(fmaf(d2, w1c.y, p.y + q.y));
            As[SWZ(d0 + 2, e)] = silu_f(fmaf(d2, w1c.z, p.z + q.z));
            As[SWZ(d0 + 3, e)] = silu_f(fmaf(d2, w1c.w, p.w + q.w));
        }
    }
    __syncthreads();

    unsigned long long acc[4][4];

    // 3) m_ij = silu(m1 @ We2 + be2); scatter to m_i and keep in Bs
    gemm_tile<128>(As, We2, be2, acc, tx, r0);
#pragma unroll
    for (int i = 0; i < 4; i++) {
        float m0[4], m1v[4];
#pragma unroll
        for (int j = 0; j < 4; j++) {
            float v0, v1; upk2(acc[i][j], v0, v1);
            m0[j] = silu_f(v0); m1v[j] = silu_f(v1);
            // pair (e, e+1) with e = r0+2i: same quad, 8B-aligned
            *(unsigned long long*)(Bs + SWZ(tx * 4 + j, r0 + 2 * i)) = pk2(m0[j], m1v[j]);
        }
        const int e0 = r0 + 2 * i, e1 = e0 + 1;
        red_add_v4(g_mi + (long long)rowi[e0] * Hdim + tx * 4, m0[0], m0[1], m0[2], m0[3]);
        red_add_v4(g_mi + (long long)rowi[e1] * Hdim + tx * 4, m1v[0], m1v[1], m1v[2], m1v[3]);
    }
    __syncthreads();

    // 4) c1 = silu(m_ij @ Wc1 + bc1); s = tanh(c1 . Wc2) * 0.1; force scatter
    gemm_tile<128>(Bs, Wc1, bc1, acc, tx, r0);
    float4 wc = __ldg((const float4*)(Wc2 + tx * 4));
    float par[8];
#pragma unroll
    for (int i = 0; i < 4; i++) {
        float p0 = 0.0f, p1 = 0.0f;
        {
            float v0, v1; upk2(acc[i][0], v0, v1);
            p0 += silu_f(v0) * wc.x; p1 += silu_f(v1) * wc.x;
        }
        {
            float v0, v1; upk2(acc[i][1], v0, v1);
            p0 += silu_f(v0) * wc.y; p1 += silu_f(v1) * wc.y;
        }
        {
            float v0, v1; upk2(acc[i][2], v0, v1);
            p0 += silu_f(v0) * wc.z; p1 += silu_f(v1) * wc.z;
        }
        {
            float v0, v1; upk2(acc[i][3], v0, v1);
            p0 += silu_f(v0) * wc.w; p1 += silu_f(v1) * wc.w;
        }
        par[2 * i] = p0; par[2 * i + 1] = p1;
    }
#pragma unroll
    for (int i = 0; i < 8; i++) {
#pragma unroll
        for (int off = 16; off > 0; off >>= 1)
            par[i] += __shfl_xor_sync(0xffffffffu, par[i], off);
    }
    if (tx == 0) {
#pragma unroll
        for (int i = 0; i < 8; i++) {
            const int e = r0 + i;
            const float s = tanhf(par[i]) * 0.1f;
            float* px = out_x + (long long)rowi[e] * 3;
            atomicAdd(px + 0, nd[0 * TILE + e] * s);
            atomicAdd(px + 1, nd[1 * TILE + e] * s);
            atomicAdd(px + 2, nd[2 * TILE + e] * s);
        }
    }
}

// ---------- node kernel: node MLP + residual + LayerNorm ----------
__global__ void __launch_bounds__(256, 2) node_kernel(
    const float* __restrict__ h,
    const float* __restrict__ Wn1, const float* __restrict__ bn1,
    const float* __restrict__ Wn2, const float* __restrict__ bn2,
    const float* __restrict__ lng, const float* __restrict__ lnb,
    float* __restrict__ out_h) {
    extern __shared__ float sm[];
    float* As = sm;               // BUF256
    float* Bs = As + BUF256;      // BUF128

    const int tid = threadIdx.x;
    const int tx = tid & 31, ty = tid >> 5;
    const int r0 = ty * 8;
    const int nb = blockIdx.x * TILE;

    for (int e = ty; e < TILE; e += 8) {
        const int node = nb + e;
        const int d0 = tx * 4;
        if (node < NNODES) {
            float4 hv = __ldg((const float4*)(h + (long long)node * Hdim + d0));
            As[SWZ(d0 + 0, e)] = hv.x;
            As[SWZ(d0 + 1, e)] = hv.y;
            As[SWZ(d0 + 2, e)] = hv.z;
            As[SWZ(d0 + 3, e)] = hv.w;
            float4 mv = *(const float4*)(g_mi + (long long)node * Hdim + d0);
            As[SWZ(Hdim + d0 + 0, e)] = mv.x;
            As[SWZ(Hdim + d0 + 1, e)] = mv.y;
            As[SWZ(Hdim + d0 + 2, e)] = mv.z;
            As[SWZ(Hdim + d0 + 3, e)] = mv.w;
        } else {
#pragma unroll
            for (int q = 0; q < 4; q++) {
                As[SWZ(d0 + q, e)] = 0.0f;
                As[SWZ(Hdim + d0 + q, e)] = 0.0f;
            }
        }
    }
    __syncthreads();

    unsigned long long acc[4][4];
    gemm_tile<256>(As, Wn1, bn1, acc, tx, r0);
#pragma unroll
    for (int i = 0; i < 4; i++) {
#pragma unroll
        for (int j = 0; j < 4; j++) {
            float v0, v1; upk2(acc[i][j], v0, v1);
            *(unsigned long long*)(Bs + SWZ(tx * 4 + j, r0 + 2 * i)) =
                pk2(silu_f(v0), silu_f(v1));
        }
    }
    __syncthreads();

    gemm_tile<128>(Bs, Wn2, bn2, acc, tx, r0);

    float v[8][4];
#pragma unroll
    for (int i = 0; i < 4; i++) {
        const int n0 = nb + r0 + 2 * i, n1 = n0 + 1;
        float4 hA = make_float4(0.f, 0.f, 0.f, 0.f);
        float4 hB = make_float4(0.f, 0.f, 0.f, 0.f);
        if (n0 < NNODES) hA = __ldg((const float4*)(h + (long long)n0 * Hdim + tx * 4));
        if (n1 < NNODES) hB = __ldg((const float4*)(h + (long long)n1 * Hdim + tx * 4));
        float v0, v1;
        upk2(acc[i][0], v0, v1); v[2 * i][0] = v0 + hA.x; v[2 * i + 1][0] = v1 + hB.x;
        upk2(acc[i][1], v0, v1); v[2 * i][1] = v0 + hA.y; v[2 * i + 1][1] = v1 + hB.y;
        upk2(acc[i][2], v0, v1); v[2 * i][2] = v0 + hA.z; v[2 * i + 1][2] = v1 + hB.z;
        upk2(acc[i][3], v0, v1); v[2 * i][3] = v0 + hA.w; v[2 * i + 1][3] = v1 + hB.w;
    }

    float4 g4 = __ldg((const float4*)(lng + tx * 4));
    float4 b4 = __ldg((const float4*)(lnb + tx * 4));
#pragma unroll
    for (int rr = 0; rr < 8; rr++) {
        float s = v[rr][0] + v[rr][1] + v[rr][2] + v[rr][3];
        float q = v[rr][0] * v[rr][0] + v[rr][1] * v[rr][1] +
                  v[rr][2] * v[rr][2] + v[rr][3] * v[rr][3];
#pragma unroll
        for (int off = 16; off > 0; off >>= 1) {
            s += __shfl_xor_sync(0xffffffffu, s, off);
            q += __shfl_xor_sync(0xffffffffu, q, off);
        }
        const float mu = s * (1.0f / 128.0f);
        const float var = q * (1.0f / 128.0f) - mu * mu;
        const float rstd = rsqrtf(var + 1e-5f);
        const int node = nb + r0 + rr;
        if (node < NNODES) {
            float4 o;
            o.x = (v[rr][0] - mu) * rstd * g4.x + b4.x;
            o.y = (v[rr][1] - mu) * rstd * g4.y + b4.y;
            o.z = (v[rr][2] - mu) * rstd * g4.z + b4.z;
            o.w = (v[rr][3] - mu) * rstd * g4.w + b4.w;
            *(float4*)(out_h + (long long)node * Hdim + tx * 4) = o;
        }
    }
}

// ---------- launch ----------
extern "C" void kernel_launch(void* const* d_in, const int* in_sizes, int n_in,
                              void* d_out, int out_size) {
    const float* h   = (const float*)d_in[0];
    const float* x   = (const float*)d_in[1];
    const void*  ei  = d_in[2];
    const float* We1 = (const float*)d_in[3];
    const float* be1 = (const float*)d_in[4];
    const float* We2 = (const float*)d_in[5];
    const float* be2 = (const float*)d_in[6];
    const float* Wc1 = (const float*)d_in[7];
    const float* bc1 = (const float*)d_in[8];
    const float* Wc2 = (const float*)d_in[9];
    const float* Wn1 = (const float*)d_in[10];
    const float* bn1 = (const float*)d_in[11];
    const float* Wn2 = (const float*)d_in[12];
    const float* bn2 = (const float*)d_in[13];
    const float* lng = (const float*)d_in[14];
    const float* lnb = (const float*)d_in[15];

    float* out_h = (float*)d_out;
    float* out_x = out_h + (long long)NNODES * Hdim;

    const int SMEM_PREP = BUF128 * 4;
    const int SMEM_EDGE = (2 * BUF128 + 3 * TILE + TILE + 2 * TILE) * 4;
    const int SMEM_NODE = (BUF256 + BUF128) * 4;

    cudaFuncSetAttribute(prep_kernel, cudaFuncAttributeMaxDynamicSharedMemorySize, SMEM_PREP);
    cudaFuncSetAttribute(edge_kernel, cudaFuncAttributeMaxDynamicSharedMemorySize, SMEM_EDGE);
    cudaFuncSetAttribute(node_kernel, cudaFuncAttributeMaxDynamicSharedMemorySize, SMEM_NODE);

    detect_kernel<<<1, 32>>>((const int*)ei);
    init_kernel<<<((long long)NNODES * Hdim + 255) / 256, 256>>>(x, out_x);
    prep_kernel<<<(NNODES + TILE - 1) / TILE, 256, SMEM_PREP>>>(h, We1, be1);
    edge_kernel<<<NEDGES / TILE, 256, SMEM_EDGE>>>(x, ei, We1, We2, be2,
                                                   Wc1, bc1, Wc2, out_x);
    node_kernel<<<(NNODES + TILE - 1) / TILE, 256, SMEM_NODE>>>(h, Wn1, bn1, Wn2, bn2,
                                                                lng, lnb, out_h);
}

// round 11
// speedup vs baseline: 1.1828x; 1.0401x over previous
#include <cuda_runtime.h>

#define Hdim 128
#define NNODES 50000
#define NEDGES 800000
#define TILE 64
#define LDA 68
// Within-row quad-XOR swizzle: element (f,e) lives at
//   f*LDA + ((e>>2) ^ ((f>>2)&15))*4 + (e&3)
// Physical offset stays in [0,63] => rows never overlap. Scalar feature-major
// stores go 16-way -> ~4-way; GEMM A-reads remain warp-uniform LDS.128.
#define SWZ(f, e) ((f) * LDA + ((((((e) >> 2)) ^ (((f) >> 2) & 15)) << 2) | ((e) & 3)))
#define BUF128 (128 * LDA)
#define BUF256 (256 * LDA)

__device__ int   g_is64;
__device__ float g_mi[(long long)NNODES * Hdim];  // segment-summed m_i scratch
__device__ float g_P [(long long)NNODES * Hdim];  // h @ We1[0:128]   + be1
__device__ float g_Q [(long long)NNODES * Hdim];  // h @ We1[128:256]

// ---------- f32x2 helpers ----------
__device__ __forceinline__ unsigned long long pk2(float lo, float hi) {
    unsigned long long r;
    asm("mov.b64 %0, {%1,%2};" : "=l"(r) : "f"(lo), "f"(hi));
    return r;
}
__device__ __forceinline__ void upk2(unsigned long long v, float& lo, float& hi) {
    asm("mov.b64 {%0,%1}, %2;" : "=f"(lo), "=f"(hi) : "l"(v));
}
#define FMA2(d, a, b) asm("fma.rn.f32x2 %0, %1, %2, %0;" : "+l"(d) : "l"(a), "l"(b))

__device__ __forceinline__ void red_add_v4(float* p, float a, float b, float c, float d) {
    asm volatile("red.global.add.v4.f32 [%0], {%1,%2,%3,%4};"
                 :: "l"(p), "f"(a), "f"(b), "f"(c), "f"(d) : "memory");
}

__device__ __forceinline__ float silu_f(float v) { return v / (1.0f + __expf(-v)); }

// ---------- GEMM tile: C[64 rows x 128 cols] = A[64 x K] * W[K x 128] (+ bias) ----------
// Quad-XOR swizzled A. Swizzle state s=(k>>2)&15 is constant within each group of
// 4 k's: computed ONCE per group in the outer loop so the inner loop is pure
// pointer-increment + 1 LDG.128 + 2 LDS.128 + 16 FFMA2.
template <int K>
__device__ __forceinline__ void gemm_tile(const float* __restrict__ As,
                                          const float* __restrict__ W,
                                          const float* __restrict__ bias,
                                          unsigned long long acc[4][4],
                                          int tx, int r0) {
    const int Q = r0 >> 2;  // even (r0 multiple of 8)
    float4 b4 = bias ? __ldg((const float4*)(bias + tx * 4))
                     : make_float4(0.f, 0.f, 0.f, 0.f);
#pragma unroll
    for (int i = 0; i < 4; i++) {
        acc[i][0] = pk2(b4.x, b4.x);
        acc[i][1] = pk2(b4.y, b4.y);
        acc[i][2] = pk2(b4.z, b4.z);
        acc[i][3] = pk2(b4.w, b4.w);
    }
#pragma unroll 2
    for (int kg = 0; kg < K / 4; kg++) {
        const int s = kg & 15;
        const float* aP0 = As + (kg * 4) * LDA + ((Q ^ s) << 2);
        const float* aQ0 = As + (kg * 4) * LDA + (((Q + 1) ^ s) << 2);
        const float* Wp = W + (long long)(kg * 4) * Hdim + tx * 4;
#pragma unroll
        for (int kk = 0; kk < 4; kk++) {
            float4 w = __ldg((const float4*)(Wp + kk * Hdim));
            unsigned long long w0 = pk2(w.x, w.x);
            unsigned long long w1 = pk2(w.y, w.y);
            unsigned long long w2 = pk2(w.z, w.z);
            unsigned long long w3 = pk2(w.w, w.w);
            ulonglong2 aP = *(const ulonglong2*)(aP0 + kk * LDA);  // rows r0..r0+3
            ulonglong2 aQ = *(const ulonglong2*)(aQ0 + kk * LDA);  // rows r0+4..r0+7
            unsigned long long a2[4] = {aP.x, aP.y, aQ.x, aQ.y};
#pragma unroll
            for (int i = 0; i < 4; i++) {
                FMA2(acc[i][0], a2[i], w0);
                FMA2(acc[i][1], a2[i], w1);
                FMA2(acc[i][2], a2[i], w2);
                FMA2(acc[i][3], a2[i], w3);
            }
        }
    }
}

// ---------- index dtype detection (int32 vs int64) ----------
__global__ void detect_kernel(const int* ei32) {
    if (blockIdx.x == 0 && threadIdx.x == 0) {
        int f = 1;
        for (int i = 0; i < 1024; i++) {
            if (ei32[2 * i + 1] != 0) { f = 0; break; }
        }
        g_is64 = f;
    }
}

// ---------- init: zero m_i scratch, seed out_x = x ----------
__global__ void init_kernel(const float* __restrict__ x, float* __restrict__ out_x) {
    long long i = (long long)blockIdx.x * blockDim.x + threadIdx.x;
    if (i < (long long)NNODES * Hdim) g_mi[i] = 0.0f;
    if (i < (long long)NNODES * 3)    out_x[i] = x[i];
}

// ---------- prep: P = h @ We1[0:128] + be1 ; Q = h @ We1[128:256] ----------
__global__ void __launch_bounds__(256) prep_kernel(
    const float* __restrict__ h,
    const float* __restrict__ We1, const float* __restrict__ be1) {
    extern __shared__ float sm[];
    float* As = sm;  // BUF128

    const int tid = threadIdx.x;
    const int tx = tid & 31, ty = tid >> 5;
    const int r0 = ty * 8;
    const int nb = blockIdx.x * TILE;

    for (int e = ty; e < TILE; e += 8) {
        const int node = nb + e;
        const int d0 = tx * 4;
        float4 hv = make_float4(0.f, 0.f, 0.f, 0.f);
        if (node < NNODES) hv = __ldg((const float4*)(h + (long long)node * Hdim + d0));
        As[SWZ(d0 + 0, e)] = hv.x;
        As[SWZ(d0 + 1, e)] = hv.y;
        As[SWZ(d0 + 2, e)] = hv.z;
        As[SWZ(d0 + 3, e)] = hv.w;
    }
    __syncthreads();

    unsigned long long acc[4][4];

    gemm_tile<128>(As, We1, be1, acc, tx, r0);
#pragma unroll
    for (int i = 0; i < 4; i++) {
        const int n0 = nb + r0 + 2 * i, n1 = n0 + 1;
        float4 oA, oB;
        float v0, v1;
        upk2(acc[i][0], v0, v1); oA.x = v0; oB.x = v1;
        upk2(acc[i][1], v0, v1); oA.y = v0; oB.y = v1;
        upk2(acc[i][2], v0, v1); oA.z = v0; oB.z = v1;
        upk2(acc[i][3], v0, v1); oA.w = v0; oB.w = v1;
        if (n0 < NNODES) *(float4*)(g_P + (long long)n0 * Hdim + tx * 4) = oA;
        if (n1 < NNODES) *(float4*)(g_P + (long long)n1 * Hdim + tx * 4) = oB;
    }

    gemm_tile<128>(As, We1 + 128 * Hdim, (const float*)0, acc, tx, r0);
#pragma unroll
    for (int i = 0; i < 4; i++) {
        const int n0 = nb + r0 + 2 * i, n1 = n0 + 1;
        float4 oA, oB;
        float v0, v1;
        upk2(acc[i][0], v0, v1); oA.x = v0; oB.x = v1;
        upk2(acc[i][1], v0, v1); oA.y = v0; oB.y = v1;
        upk2(acc[i][2], v0, v1); oA.z = v0; oB.z = v1;
        upk2(acc[i][3], v0, v1); oA.w = v0; oB.w = v1;
        if (n0 < NNODES) *(float4*)(g_Q + (long long)n0 * Hdim + tx * 4) = oA;
        if (n1 < NNODES) *(float4*)(g_Q + (long long)n1 * Hdim + tx * 4) = oB;
    }
}

// ---------- edge kernel (R5 structure + quad-XOR swizzled smem) ----------
__global__ void __launch_bounds__(256, 3) edge_kernel(
    const float* __restrict__ x, const void* __restrict__ ei,
    const float* __restrict__ We1,
    const float* __restrict__ We2, const float* __restrict__ be2,
    const float* __restrict__ Wc1, const float* __restrict__ bc1,
    const float* __restrict__ Wc2,
    float* __restrict__ out_x) {
    extern __shared__ float sm[];
    float* As = sm;                      // BUF128 (m1)
    float* Bs = As + BUF128;             // BUF128 (m_ij)
    float* nd = Bs + BUF128;             // 3 * TILE
    float* d2s = nd + 3 * TILE;          // TILE
    int*  rowi = (int*)(d2s + TILE);     // TILE
    int*  coli = rowi + TILE;            // TILE

    const int tid = threadIdx.x;
    const int tx = tid & 31, ty = tid >> 5;
    const int r0 = ty * 8;
    const int eb = blockIdx.x * TILE;
    const int is64 = g_is64;

    // 1) indices + coord geometry
    if (tid < TILE) {
        int e = tid;
        long long r, c;
        if (is64) {
            const long long* p = (const long long*)ei;
            r = p[eb + e]; c = p[NEDGES + eb + e];
        } else {
            const int* p = (const int*)ei;
            r = p[eb + e]; c = p[NEDGES + eb + e];
        }
        rowi[e] = (int)r; coli[e] = (int)c;
        float dx = __ldg(x + r * 3 + 0) - __ldg(x + c * 3 + 0);
        float dy = __ldg(x + r * 3 + 1) - __ldg(x + c * 3 + 1);
        float dz = __ldg(x + r * 3 + 2) - __ldg(x + c * 3 + 2);
        float d2 = dx * dx + dy * dy + dz * dz;
        float dist = sqrtf(d2);
        d2s[e] = d2;
        float inv = 1.0f / (dist + 1e-8f);
        nd[0 * TILE + e] = dx * inv;
        nd[1 * TILE + e] = dy * inv;
        nd[2 * TILE + e] = dz * inv;
    }
    __syncthreads();

    // 2) m1 = silu(P[row] + Q[col] + d2 * We1[256])
    {
        const int d0 = tx * 4;
        float4 w1c = __ldg((const float4*)(We1 + 256 * Hdim + d0));
        for (int e = ty; e < TILE; e += 8) {
            const long long rr = rowi[e], cc = coli[e];
            float4 p = __ldg((const float4*)(g_P + rr * Hdim + d0));
            float4 q = __ldg((const float4*)(g_Q + cc * Hdim + d0));
            const float d2 = d2s[e];
            As[SWZ(d0 + 0, e)] = silu_f(fmaf(d2, w1c.x, p.x + q.x));
            As[SWZ(d0 + 1, e)] = silu_f(fmaf(d2, w1c.y, p.y + q.y));
            As[SWZ(d0 + 2, e)] = silu_f(fmaf(d2, w1c.z, p.z + q.z));
            As[SWZ(d0 + 3, e)] = silu_f(fmaf(d2, w1c.w, p.w + q.w));
        }
    }
    __syncthreads();

    unsigned long long acc[4][4];

    // 3) m_ij = silu(m1 @ We2 + be2); scatter to m_i and keep in Bs
    gemm_tile<128>(As, We2, be2, acc, tx, r0);
#pragma unroll
    for (int i = 0; i < 4; i++) {
        float m0[4], m1v[4];
#pragma unroll
        for (int j = 0; j < 4; j++) {
            float v0, v1; upk2(acc[i][j], v0, v1);
            m0[j] = silu_f(v0); m1v[j] = silu_f(v1);
            // pair (e, e+1) with e = r0+2i: same quad, 8B-aligned
            *(unsigned long long*)(Bs + SWZ(tx * 4 + j, r0 + 2 * i)) = pk2(m0[j], m1v[j]);
        }
        const int e0 = r0 + 2 * i, e1 = e0 + 1;
        red_add_v4(g_mi + (long long)rowi[e0] * Hdim + tx * 4, m0[0], m0[1], m0[2], m0[3]);
        red_add_v4(g_mi + (long long)rowi[e1] * Hdim + tx * 4, m1v[0], m1v[1], m1v[2], m1v[3]);
    }
    __syncthreads();

    // 4) c1 = silu(m_ij @ Wc1 + bc1); s = tanh(c1 . Wc2) * 0.1; force scatter
    gemm_tile<128>(Bs, Wc1, bc1, acc, tx, r0);
    float4 wc = __ldg((const float4*)(Wc2 + tx * 4));
    float par[8];
#pragma unroll
    for (int i = 0; i < 4; i++) {
        float p0 = 0.0f, p1 = 0.0f;
        {
            float v0, v1; upk2(acc[i][0], v0, v1);
            p0 += silu_f(v0) * wc.x; p1 += silu_f(v1) * wc.x;
        }
        {
            float v0, v1; upk2(acc[i][1], v0, v1);
            p0 += silu_f(v0) * wc.y; p1 += silu_f(v1) * wc.y;
        }
        {
            float v0, v1; upk2(acc[i][2], v0, v1);
            p0 += silu_f(v0) * wc.z; p1 += silu_f(v1) * wc.z;
        }
        {
            float v0, v1; upk2(acc[i][3], v0, v1);
            p0 += silu_f(v0) * wc.w; p1 += silu_f(v1) * wc.w;
        }
        par[2 * i] = p0; par[2 * i + 1] = p1;
    }
#pragma unroll
    for (int i = 0; i < 8; i++) {
#pragma unroll
        for (int off = 16; off > 0; off >>= 1)
            par[i] += __shfl_xor_sync(0xffffffffu, par[i], off);
    }
    if (tx == 0) {
#pragma unroll
        for (int i = 0; i < 8; i++) {
            const int e = r0 + i;
            const float s = tanhf(par[i]) * 0.1f;
            float* px = out_x + (long long)rowi[e] * 3;
            atomicAdd(px + 0, nd[0 * TILE + e] * s);
            atomicAdd(px + 1, nd[1 * TILE + e] * s);
            atomicAdd(px + 2, nd[2 * TILE + e] * s);
        }
    }
}

// ---------- node kernel: node MLP + residual + LayerNorm ----------
__global__ void __launch_bounds__(256, 2) node_kernel(
    const float* __restrict__ h,
    const float* __restrict__ Wn1, const float* __restrict__ bn1,
    const float* __restrict__ Wn2, const float* __restrict__ bn2,
    const float* __restrict__ lng, const float* __restrict__ lnb,
    float* __restrict__ out_h) {
    extern __shared__ float sm[];
    float* As = sm;               // BUF256
    float* Bs = As + BUF256;      // BUF128

    const int tid = threadIdx.x;
    const int tx = tid & 31, ty = tid >> 5;
    const int r0 = ty * 8;
    const int nb = blockIdx.x * TILE;

    for (int e = ty; e < TILE; e += 8) {
        const int node = nb + e;
        const int d0 = tx * 4;
        if (node < NNODES) {
            float4 hv = __ldg((const float4*)(h + (long long)node * Hdim + d0));
            As[SWZ(d0 + 0, e)] = hv.x;
            As[SWZ(d0 + 1, e)] = hv.y;
            As[SWZ(d0 + 2, e)] = hv.z;
            As[SWZ(d0 + 3, e)] = hv.w;
            float4 mv = *(const float4*)(g_mi + (long long)node * Hdim + d0);
            As[SWZ(Hdim + d0 + 0, e)] = mv.x;
            As[SWZ(Hdim + d0 + 1, e)] = mv.y;
            As[SWZ(Hdim + d0 + 2, e)] = mv.z;
            As[SWZ(Hdim + d0 + 3, e)] = mv.w;
        } else {
#pragma unroll
            for (int q = 0; q < 4; q++) {
                As[SWZ(d0 + q, e)] = 0.0f;
                As[SWZ(Hdim + d0 + q, e)] = 0.0f;
            }
        }
    }
    __syncthreads();

    unsigned long long acc[4][4];
    gemm_tile<256>(As, Wn1, bn1, acc, tx, r0);
#pragma unroll
    for (int i = 0; i < 4; i++) {
#pragma unroll
        for (int j = 0; j < 4; j++) {
            float v0, v1; upk2(acc[i][j], v0, v1);
            *(unsigned long long*)(Bs + SWZ(tx * 4 + j, r0 + 2 * i)) =
                pk2(silu_f(v0), silu_f(v1));
        }
    }
    __syncthreads();

    gemm_tile<128>(Bs, Wn2, bn2, acc, tx, r0);

    float v[8][4];
#pragma unroll
    for (int i = 0; i < 4; i++) {
        const int n0 = nb + r0 + 2 * i, n1 = n0 + 1;
        float4 hA = make_float4(0.f, 0.f, 0.f, 0.f);
        float4 hB = make_float4(0.f, 0.f, 0.f, 0.f);
        if (n0 < NNODES) hA = __ldg((const float4*)(h + (long long)n0 * Hdim + tx * 4));
        if (n1 < NNODES) hB = __ldg((const float4*)(h + (long long)n1 * Hdim + tx * 4));
        float v0, v1;
        upk2(acc[i][0], v0, v1); v[2 * i][0] = v0 + hA.x; v[2 * i + 1][0] = v1 + hB.x;
        upk2(acc[i][1], v0, v1); v[2 * i][1] = v0 + hA.y; v[2 * i + 1][1] = v1 + hB.y;
        upk2(acc[i][2], v0, v1); v[2 * i][2] = v0 + hA.z; v[2 * i + 1][2] = v1 + hB.z;
        upk2(acc[i][3], v0, v1); v[2 * i][3] = v0 + hA.w; v[2 * i + 1][3] = v1 + hB.w;
    }

    float4 g4 = __ldg((const float4*)(lng + tx * 4));
    float4 b4 = __ldg((const float4*)(lnb + tx * 4));
#pragma unroll
    for (int rr = 0; rr < 8; rr++) {
        float s = v[rr][0] + v[rr][1] + v[rr][2] + v[rr][3];
        float q = v[rr][0] * v[rr][0] + v[rr][1] * v[rr][1] +
                  v[rr][2] * v[rr][2] + v[rr][3] * v[rr][3];
#pragma unroll
        for (int off = 16; off > 0; off >>= 1) {
            s += __shfl_xor_sync(0xffffffffu, s, off);
            q += __shfl_xor_sync(0xffffffffu, q, off);
        }
        const float mu = s * (1.0f / 128.0f);
        const float var = q * (1.0f / 128.0f) - mu * mu;
        const float rstd = rsqrtf(var + 1e-5f);
        const int node = nb + r0 + rr;
        if (node < NNODES) {
            float4 o;
            o.x = (v[rr][0] - mu) * rstd * g4.x + b4.x;
            o.y = (v[rr][1] - mu) * rstd * g4.y + b4.y;
            o.z = (v[rr][2] - mu) * rstd * g4.z + b4.z;
            o.w = (v[rr][3] - mu) * rstd * g4.w + b4.w;
            *(float4*)(out_h + (long long)node * Hdim + tx * 4) = o;
        }
    }
}

// ---------- launch ----------
extern "C" void kernel_launch(void* const* d_in, const int* in_sizes, int n_in,
                              void* d_out, int out_size) {
    const float* h   = (const float*)d_in[0];
    const float* x   = (const float*)d_in[1];
    const void*  ei  = d_in[2];
    const float* We1 = (const float*)d_in[3];
    const float* be1 = (const float*)d_in[4];
    const float* We2 = (const float*)d_in[5];
    const float* be2 = (const float*)d_in[6];
    const float* Wc1 = (const float*)d_in[7];
    const float* bc1 = (const float*)d_in[8];
    const float* Wc2 = (const float*)d_in[9];
    const float* Wn1 = (const float*)d_in[10];
    const float* bn1 = (const float*)d_in[11];
    const float* Wn2 = (const float*)d_in[12];
    const float* bn2 = (const float*)d_in[13];
    const float* lng = (const float*)d_in[14];
    const float* lnb = (const float*)d_in[15];

    float* out_h = (float*)d_out;
    float* out_x = out_h + (long long)NNODES * Hdim;

    const int SMEM_PREP = BUF128 * 4;
    const int SMEM_EDGE = (2 * BUF128 + 3 * TILE + TILE + 2 * TILE) * 4;
    const int SMEM_NODE = (BUF256 + BUF128) * 4;

    cudaFuncSetAttribute(prep_kernel, cudaFuncAttributeMaxDynamicSharedMemorySize, SMEM_PREP);
    cudaFuncSetAttribute(edge_kernel, cudaFuncAttributeMaxDynamicSharedMemorySize, SMEM_EDGE);
    cudaFuncSetAttribute(node_kernel, cudaFuncAttributeMaxDynamicSharedMemorySize, SMEM_NODE);

    detect_kernel<<<1, 32>>>((const int*)ei);
    init_kernel<<<((long long)NNODES * Hdim + 255) / 256, 256>>>(x, out_x);
    prep_kernel<<<(NNODES + TILE - 1) / TILE, 256, SMEM_PREP>>>(h, We1, be1);
    edge_kernel<<<NEDGES / TILE, 256, SMEM_EDGE>>>(x, ei, We1, We2, be2,
                                                   Wc1, bc1, Wc2, out_x);
    node_kernel<<<(NNODES + TILE - 1) / TILE, 256, SMEM_NODE>>>(h, Wn1, bn1, Wn2, bn2,
                                                                lng, lnb, out_h);
}

// round 14
// speedup vs baseline: 1.5939x; 1.3475x over previous
#include <cuda_runtime.h>
#include <cuda_bf16.h>
#include <cstdint>

#define Hdim 128
#define NNODES 50000
#define NEDGES 800000
#define TILE 64
#define LDA 68
#define SWZ(f, e) ((f) * LDA + ((((((e) >> 2)) ^ (((f) >> 2) & 15)) << 2) | ((e) & 3)))
#define BUF128 (128 * LDA)
#define BUF256 (256 * LDA)

// ---- HMMA edge kernel ----
#define ET 128            // edges per CTA (16 per warp)
#define AROWB 272         // A-tile row pitch in bytes (136 bf16) -> conflict-free frags
#define EB_ROWI 0
#define EB_COLI 512
#define EB_D2S  1024
#define EB_ND   1536
#define EB_AHI  3072
#define EB_ALO  (EB_AHI + 128 * AROWB)
#define EB_TOTAL (EB_ALO + 128 * AROWB)

__device__ int   g_is64;
__device__ float g_mi[(long long)NNODES * Hdim];
__device__ float g_P [(long long)NNODES * Hdim];
__device__ float g_Q [(long long)NNODES * Hdim];
// W fragments: [0]=We2_hi [1]=We2_lo [2]=Wc1_hi [3]=Wc1_lo.
// Index: [(kt*16+nt)*32 + lane] -> uint2{b0,b1} per m16n8k16 B-fragment layout.
__device__ __align__(16) uint2 g_WF[4][4096];

// ---------- f32x2 helpers (prep/node FFMA path) ----------
__device__ __forceinline__ unsigned long long pk2(float lo, float hi) {
    unsigned long long r;
    asm("mov.b64 %0, {%1,%2};" : "=l"(r) : "f"(lo), "f"(hi));
    return r;
}
__device__ __forceinline__ void upk2(unsigned long long v, float& lo, float& hi) {
    asm("mov.b64 {%0,%1}, %2;" : "=f"(lo), "=f"(hi) : "l"(v));
}
#define FMA2(d, a, b) asm("fma.rn.f32x2 %0, %1, %2, %0;" : "+l"(d) : "l"(a), "l"(b))

__device__ __forceinline__ void red_add_v2(float* p, float a, float b) {
    asm volatile("red.global.add.v2.f32 [%0], {%1,%2};"
                 :: "l"(p), "f"(a), "f"(b) : "memory");
}
__device__ __forceinline__ float silu_f(float v) { return v / (1.0f + __expf(-v)); }

// hi/lo bf16 split: returns packed bf16x2 of (a,b) hi parts, residuals out.
__device__ __forceinline__ uint32_t split_hi(float a, float b, float& ra, float& rb) {
    __nv_bfloat162 h = __floats2bfloat162_rn(a, b);
    ra = a - __bfloat162float(h.x);
    rb = b - __bfloat162float(h.y);
    return *reinterpret_cast<uint32_t*>(&h);
}
__device__ __forceinline__ uint32_t pack_bf(float a, float b) {
    __nv_bfloat162 h = __floats2bfloat162_rn(a, b);
    return *reinterpret_cast<uint32_t*>(&h);
}

// ---------- mma.sync m16n8k16 bf16 (baseline PTX, runs on HMMA) ----------
__device__ __forceinline__ void mma16816(float d[4], const uint32_t a[4],
                                         uint32_t b0, uint32_t b1) {
    asm volatile(
        "mma.sync.aligned.m16n8k16.row.col.f32.bf16.bf16.f32 "
        "{%0,%1,%2,%3}, {%4,%5,%6,%7}, {%8,%9}, {%0,%1,%2,%3};"
        : "+f"(d[0]), "+f"(d[1]), "+f"(d[2]), "+f"(d[3])
        : "r"(a[0]), "r"(a[1]), "r"(a[2]), "r"(a[3]), "r"(b0), "r"(b1));
}

// ---------- prep/node GEMM tile (R10-proven FFMA) ----------
template <int K>
__device__ __forceinline__ void gemm_tile(const float* __restrict__ As,
                                          const float* __restrict__ W,
                                          const float* __restrict__ bias,
                                          unsigned long long acc[4][4],
                                          int tx, int r0) {
    const int Q = r0 >> 2;
    float4 b4 = bias ? __ldg((const float4*)(bias + tx * 4))
                     : make_float4(0.f, 0.f, 0.f, 0.f);
#pragma unroll
    for (int i = 0; i < 4; i++) {
        acc[i][0] = pk2(b4.x, b4.x);
        acc[i][1] = pk2(b4.y, b4.y);
        acc[i][2] = pk2(b4.z, b4.z);
        acc[i][3] = pk2(b4.w, b4.w);
    }
#pragma unroll 2
    for (int kg = 0; kg < K / 4; kg++) {
        const int s = kg & 15;
        const float* aP0 = As + (kg * 4) * LDA + ((Q ^ s) << 2);
        const float* aQ0 = As + (kg * 4) * LDA + (((Q + 1) ^ s) << 2);
        const float* Wp = W + (long long)(kg * 4) * Hdim + tx * 4;
#pragma unroll
        for (int kk = 0; kk < 4; kk++) {
            float4 w = __ldg((const float4*)(Wp + kk * Hdim));
            unsigned long long w0 = pk2(w.x, w.x);
            unsigned long long w1 = pk2(w.y, w.y);
            unsigned long long w2 = pk2(w.z, w.z);
            unsigned long long w3 = pk2(w.w, w.w);
            ulonglong2 aP = *(const ulonglong2*)(aP0 + kk * LDA);
            ulonglong2 aQ = *(const ulonglong2*)(aQ0 + kk * LDA);
            unsigned long long a2[4] = {aP.x, aP.y, aQ.x, aQ.y};
#pragma unroll
            for (int i = 0; i < 4; i++) {
                FMA2(acc[i][0], a2[i], w0);
                FMA2(acc[i][1], a2[i], w1);
                FMA2(acc[i][2], a2[i], w2);
                FMA2(acc[i][3], a2[i], w3);
            }
        }
    }
}

// ---------- index dtype detection ----------
__global__ void detect_kernel(const int* ei32) {
    if (blockIdx.x == 0 && threadIdx.x == 0) {
        int f = 1;
        for (int i = 0; i < 1024; i++) {
            if (ei32[2 * i + 1] != 0) { f = 0; break; }
        }
        g_is64 = f;
    }
}

// ---------- init ----------
__global__ void init_kernel(const float* __restrict__ x, float* __restrict__ out_x) {
    long long i = (long long)blockIdx.x * blockDim.x + threadIdx.x;
    if (i < (long long)NNODES * Hdim) g_mi[i] = 0.0f;
    if (i < (long long)NNODES * 3)    out_x[i] = x[i];
}

// ---------- weight fragment pre-pack ----------
// One thread per (mat, kt, nt, lane). B fragment (m16n8k16 .col):
//   b0 = (W[16kt+2t][8nt+g], W[16kt+2t+1][8nt+g])
//   b1 = (W[16kt+2t+8][8nt+g], W[16kt+2t+9][8nt+g]),  g=lane>>2, t=lane&3.
__global__ void wsetup_kernel(const float* __restrict__ We2, const float* __restrict__ Wc1) {
    int id = blockIdx.x * blockDim.x + threadIdx.x;
    if (id >= 8192) return;
    int lane = id & 31, nt = (id >> 5) & 15, kt = (id >> 9) & 7, mat = id >> 12;
    int g = lane >> 2, t = lane & 3;
    const float* W = mat ? Wc1 : We2;
    int n = nt * 8 + g;
    float w00 = W[(kt * 16 + 2 * t + 0) * Hdim + n];
    float w01 = W[(kt * 16 + 2 * t + 1) * Hdim + n];
    float w10 = W[(kt * 16 + 2 * t + 8) * Hdim + n];
    float w11 = W[(kt * 16 + 2 * t + 9) * Hdim + n];
    float r00, r01, r10, r11;
    uint32_t h0 = split_hi(w00, w01, r00, r01);
    uint32_t h1 = split_hi(w10, w11, r10, r11);
    uint32_t l0 = pack_bf(r00, r01);
    uint32_t l1 = pack_bf(r10, r11);
    int idx = (kt * 16 + nt) * 32 + lane;
    g_WF[mat * 2 + 0][idx] = make_uint2(h0, h1);
    g_WF[mat * 2 + 1][idx] = make_uint2(l0, l1);
}

// ---------- prep: P = h @ We1[0:128] + be1 ; Q = h @ We1[128:256] (R10-proven) ----------
__global__ void __launch_bounds__(256) prep_kernel(
    const float* __restrict__ h,
    const float* __restrict__ We1, const float* __restrict__ be1) {
    extern __shared__ float sm[];
    float* As = sm;

    const int tid = threadIdx.x;
    const int tx = tid & 31, ty = tid >> 5;
    const int r0 = ty * 8;
    const int nb = blockIdx.x * TILE;

    for (int e = ty; e < TILE; e += 8) {
        const int node = nb + e;
        const int d0 = tx * 4;
        float4 hv = make_float4(0.f, 0.f, 0.f, 0.f);
        if (node < NNODES) hv = __ldg((const float4*)(h + (long long)node * Hdim + d0));
        As[SWZ(d0 + 0, e)] = hv.x;
        As[SWZ(d0 + 1, e)] = hv.y;
        As[SWZ(d0 + 2, e)] = hv.z;
        As[SWZ(d0 + 3, e)] = hv.w;
    }
    __syncthreads();

    unsigned long long acc[4][4];

    gemm_tile<128>(As, We1, be1, acc, tx, r0);
#pragma unroll
    for (int i = 0; i < 4; i++) {
        const int n0 = nb + r0 + 2 * i, n1 = n0 + 1;
        float4 oA, oB;
        float v0, v1;
        upk2(acc[i][0], v0, v1); oA.x = v0; oB.x = v1;
        upk2(acc[i][1], v0, v1); oA.y = v0; oB.y = v1;
        upk2(acc[i][2], v0, v1); oA.z = v0; oB.z = v1;
        upk2(acc[i][3], v0, v1); oA.w = v0; oB.w = v1;
        if (n0 < NNODES) *(float4*)(g_P + (long long)n0 * Hdim + tx * 4) = oA;
        if (n1 < NNODES) *(float4*)(g_P + (long long)n1 * Hdim + tx * 4) = oB;
    }

    gemm_tile<128>(As, We1 + 128 * Hdim, (const float*)0, acc, tx, r0);
#pragma unroll
    for (int i = 0; i < 4; i++) {
        const int n0 = nb + r0 + 2 * i, n1 = n0 + 1;
        float4 oA, oB;
        float v0, v1;
        upk2(acc[i][0], v0, v1); oA.x = v0; oB.x = v1;
        upk2(acc[i][1], v0, v1); oA.y = v0; oB.y = v1;
        upk2(acc[i][2], v0, v1); oA.z = v0; oB.z = v1;
        upk2(acc[i][3], v0, v1); oA.w = v0; oB.w = v1;
        if (n0 < NNODES) *(float4*)(g_Q + (long long)n0 * Hdim + tx * 4) = oA;
        if (n1 < NNODES) *(float4*)(g_Q + (long long)n1 * Hdim + tx * 4) = oB;
    }
}

// ---------- HMMA GEMM over the warp's 16-edge A tile: d[nt][4] += A @ W(frag) ----------
__device__ __forceinline__ void gemm_mma(const char* smc, const uint2* __restrict__ WFh,
                                         const uint2* __restrict__ WFl,
                                         float d[16][4], int e0, int lane) {
    const int g = lane >> 2, t = lane & 3;
#pragma unroll
    for (int nt = 0; nt < 16; nt++)
#pragma unroll
        for (int j = 0; j < 4; j++) d[nt][j] = 0.0f;
    const char* rowg = smc + EB_AHI + (e0 + g) * AROWB;
    const char* row8 = rowg + 8 * AROWB;
#pragma unroll 1
    for (int kt = 0; kt < 8; kt++) {
        const int kb = kt * 32 + t * 4;
        uint32_t ah[4], al[4];
        ah[0] = *(const uint32_t*)(rowg + kb);
        ah[1] = *(const uint32_t*)(row8 + kb);
        ah[2] = *(const uint32_t*)(rowg + kb + 16);
        ah[3] = *(const uint32_t*)(row8 + kb + 16);
        al[0] = *(const uint32_t*)(rowg + (EB_ALO - EB_AHI) + kb);
        al[1] = *(const uint32_t*)(row8 + (EB_ALO - EB_AHI) + kb);
        al[2] = *(const uint32_t*)(rowg + (EB_ALO - EB_AHI) + kb + 16);
        al[3] = *(const uint32_t*)(row8 + (EB_ALO - EB_AHI) + kb + 16);
        const uint2* fh = WFh + kt * 16 * 32 + lane;
        const uint2* fl = WFl + kt * 16 * 32 + lane;
#pragma unroll
        for (int nt = 0; nt < 16; nt++) {
            uint2 bh = __ldg(fh + nt * 32);
            uint2 bl = __ldg(fl + nt * 32);
            mma16816(d[nt], ah, bh.x, bh.y);
            mma16816(d[nt], ah, bl.x, bl.y);
            mma16816(d[nt], al, bh.x, bh.y);
        }
    }
}

// ---------- HMMA edge kernel: 128 edges/CTA, warp-independent after geometry ----------
__global__ void __launch_bounds__(256) edge_mma_kernel(
    const float* __restrict__ x, const void* __restrict__ ei,
    const float* __restrict__ We1,
    const float* __restrict__ be2, const float* __restrict__ bc1,
    const float* __restrict__ Wc2,
    float* __restrict__ out_x) {
    extern __shared__ float sm[];
    char* smc = (char*)sm;
    int*   rowi = (int*)(smc + EB_ROWI);
    int*   coli = (int*)(smc + EB_COLI);
    float* d2s  = (float*)(smc + EB_D2S);
    float* nd   = (float*)(smc + EB_ND);

    const int tid = threadIdx.x, wid = tid >> 5, lane = tid & 31;
    const int g = lane >> 2, t = lane & 3;
    const int e0 = wid * 16;
    const int eb = blockIdx.x * ET;
    const int is64 = g_is64;

    // geometry (tid<128 covers 128 edges)
    if (tid < ET) {
        int e = tid;
        long long r, c;
        if (is64) {
            const long long* p = (const long long*)ei;
            r = p[eb + e]; c = p[NEDGES + eb + e];
        } else {
            const int* p = (const int*)ei;
            r = p[eb + e]; c = p[NEDGES + eb + e];
        }
        rowi[e] = (int)r; coli[e] = (int)c;
        float dx = __ldg(x + r * 3 + 0) - __ldg(x + c * 3 + 0);
        float dy = __ldg(x + r * 3 + 1) - __ldg(x + c * 3 + 1);
        float dz = __ldg(x + r * 3 + 2) - __ldg(x + c * 3 + 2);
        float d2 = dx * dx + dy * dy + dz * dz;
        float dist = sqrtf(d2);
        d2s[e] = d2;
        float inv = 1.0f / (dist + 1e-8f);
        nd[0 * ET + e] = dx * inv;
        nd[1 * ET + e] = dy * inv;
        nd[2 * ET + e] = dz * inv;
    }
    __syncthreads();

    // m1 gather for this warp's 16 edges; split hi/lo into A tiles
    {
        const int k0 = lane * 4;
        float4 w1c = __ldg((const float4*)(We1 + 256 * Hdim + k0));
#pragma unroll 2
        for (int e = 0; e < 16; e++) {
            const int er = e0 + e;
            const long long rr = rowi[er], cc = coli[er];
            float4 p = __ldg((const float4*)(g_P + rr * Hdim + k0));
            float4 q = __ldg((const float4*)(g_Q + cc * Hdim + k0));
            const float d2 = d2s[er];
            float m0 = silu_f(fmaf(d2, w1c.x, p.x + q.x));
            float m1 = silu_f(fmaf(d2, w1c.y, p.y + q.y));
            float m2 = silu_f(fmaf(d2, w1c.z, p.z + q.z));
            float m3 = silu_f(fmaf(d2, w1c.w, p.w + q.w));
            float r0, r1, r2, r3;
            uint32_t h01 = split_hi(m0, m1, r0, r1);
            uint32_t h23 = split_hi(m2, m3, r2, r3);
            uint32_t l01 = pack_bf(r0, r1);
            uint32_t l23 = pack_bf(r2, r3);
            *(uint2*)(smc + EB_AHI + er * AROWB + lane * 8) = make_uint2(h01, h23);
            *(uint2*)(smc + EB_ALO + er * AROWB + lane * 8) = make_uint2(l01, l23);
        }
    }
    __syncwarp();

    float d[16][4];

    // GEMM1: D = m1 @ We2
    gemm_mma(smc, g_WF[0], g_WF[1], d, e0, lane);

    // epilogue1: m_ij = silu(D + be2); red_add to g_mi; re-split into A tiles
    {
        const long long rg = (long long)rowi[e0 + g] * Hdim;
        const long long r8 = (long long)rowi[e0 + g + 8] * Hdim;
#pragma unroll
        for (int nt = 0; nt < 16; nt++) {
            const int c0 = nt * 8 + 2 * t;
            float2 b2 = __ldg((const float2*)(be2 + c0));
            float m00 = silu_f(d[nt][0] + b2.x);
            float m01 = silu_f(d[nt][1] + b2.y);
            float m10 = silu_f(d[nt][2] + b2.x);
            float m11 = silu_f(d[nt][3] + b2.y);
            red_add_v2(g_mi + rg + c0, m00, m01);
            red_add_v2(g_mi + r8 + c0, m10, m11);
            float q0, q1, q2, q3;
            uint32_t h0 = split_hi(m00, m01, q0, q1);
            uint32_t h1 = split_hi(m10, m11, q2, q3);
            const int og = (e0 + g) * AROWB + c0 * 2;
            const int o8 = (e0 + g + 8) * AROWB + c0 * 2;
            *(uint32_t*)(smc + EB_AHI + og) = h0;
            *(uint32_t*)(smc + EB_AHI + o8) = h1;
            *(uint32_t*)(smc + EB_ALO + og) = pack_bf(q0, q1);
            *(uint32_t*)(smc + EB_ALO + o8) = pack_bf(q2, q3);
        }
    }
    __syncwarp();

    // GEMM2: D = m_ij @ Wc1
    gemm_mma(smc, g_WF[2], g_WF[3], d, e0, lane);

    // epilogue2: s = tanh(silu(D + bc1) . Wc2) * 0.1; force scatter
    {
        float sl = 0.0f, sh = 0.0f;
#pragma unroll
        for (int nt = 0; nt < 16; nt++) {
            const int c0 = nt * 8 + 2 * t;
            float2 bb = __ldg((const float2*)(bc1 + c0));
            float2 wc = __ldg((const float2*)(Wc2 + c0));
            sl = fmaf(silu_f(d[nt][0] + bb.x), wc.x, sl);
            sl = fmaf(silu_f(d[nt][1] + bb.y), wc.y, sl);
            sh = fmaf(silu_f(d[nt][2] + bb.x), wc.x, sh);
            sh = fmaf(silu_f(d[nt][3] + bb.y), wc.y, sh);
        }
        sl += __shfl_xor_sync(0xffffffffu, sl, 1);
        sl += __shfl_xor_sync(0xffffffffu, sl, 2);
        sh += __shfl_xor_sync(0xffffffffu, sh, 1);
        sh += __shfl_xor_sync(0xffffffffu, sh, 2);
        if (t == 0) {
            const int eg = e0 + g, e8 = e0 + g + 8;
            const float s0 = tanhf(sl) * 0.1f;
            const float s1 = tanhf(sh) * 0.1f;
            float* p0 = out_x + (long long)rowi[eg] * 3;
            float* p1 = out_x + (long long)rowi[e8] * 3;
            atomicAdd(p0 + 0, nd[0 * ET + eg] * s0);
            atomicAdd(p0 + 1, nd[1 * ET + eg] * s0);
            atomicAdd(p0 + 2, nd[2 * ET + eg] * s0);
            atomicAdd(p1 + 0, nd[0 * ET + e8] * s1);
            atomicAdd(p1 + 1, nd[1 * ET + e8] * s1);
            atomicAdd(p1 + 2, nd[2 * ET + e8] * s1);
        }
    }
}

// ---------- node kernel (R10-proven) ----------
__global__ void __launch_bounds__(256, 2) node_kernel(
    const float* __restrict__ h,
    const float* __restrict__ Wn1, const float* __restrict__ bn1,
    const float* __restrict__ Wn2, const float* __restrict__ bn2,
    const float* __restrict__ lng, const float* __restrict__ lnb,
    float* __restrict__ out_h) {
    extern __shared__ float sm[];
    float* As = sm;
    float* Bs = As + BUF256;

    const int tid = threadIdx.x;
    const int tx = tid & 31, ty = tid >> 5;
    const int r0 = ty * 8;
    const int nb = blockIdx.x * TILE;

    for (int e = ty; e < TILE; e += 8) {
        const int node = nb + e;
        const int d0 = tx * 4;
        if (node < NNODES) {
            float4 hv = __ldg((const float4*)(h + (long long)node * Hdim + d0));
            As[SWZ(d0 + 0, e)] = hv.x;
            As[SWZ(d0 + 1, e)] = hv.y;
            As[SWZ(d0 + 2, e)] = hv.z;
            As[SWZ(d0 + 3, e)] = hv.w;
            float4 mv = *(const float4*)(g_mi + (long long)node * Hdim + d0);
            As[SWZ(Hdim + d0 + 0, e)] = mv.x;
            As[SWZ(Hdim + d0 + 1, e)] = mv.y;
            As[SWZ(Hdim + d0 + 2, e)] = mv.z;
            As[SWZ(Hdim + d0 + 3, e)] = mv.w;
        } else {
#pragma unroll
            for (int q = 0; q < 4; q++) {
                As[SWZ(d0 + q, e)] = 0.0f;
                As[SWZ(Hdim + d0 + q, e)] = 0.0f;
            }
        }
    }
    __syncthreads();

    unsigned long long acc[4][4];
    gemm_tile<256>(As, Wn1, bn1, acc, tx, r0);
#pragma unroll
    for (int i = 0; i < 4; i++) {
#pragma unroll
        for (int j = 0; j < 4; j++) {
            float v0, v1; upk2(acc[i][j], v0, v1);
            *(unsigned long long*)(Bs + SWZ(tx * 4 + j, r0 + 2 * i)) =
                pk2(silu_f(v0), silu_f(v1));
        }
    }
    __syncthreads();

    gemm_tile<128>(Bs, Wn2, bn2, acc, tx, r0);

    float v[8][4];
#pragma unroll
    for (int i = 0; i < 4; i++) {
        const int n0 = nb + r0 + 2 * i, n1 = n0 + 1;
        float4 hA = make_float4(0.f, 0.f, 0.f, 0.f);
        float4 hB = make_float4(0.f, 0.f, 0.f, 0.f);
        if (n0 < NNODES) hA = __ldg((const float4*)(h + (long long)n0 * Hdim + tx * 4));
        if (n1 < NNODES) hB = __ldg((const float4*)(h + (long long)n1 * Hdim + tx * 4));
        float v0, v1;
        upk2(acc[i][0], v0, v1); v[2 * i][0] = v0 + hA.x; v[2 * i + 1][0] = v1 + hB.x;
        upk2(acc[i][1], v0, v1); v[2 * i][1] = v0 + hA.y; v[2 * i + 1][1] = v1 + hB.y;
        upk2(acc[i][2], v0, v1); v[2 * i][2] = v0 + hA.z; v[2 * i + 1][2] = v1 + hB.z;
        upk2(acc[i][3], v0, v1); v[2 * i][3] = v0 + hA.w; v[2 * i + 1][3] = v1 + hB.w;
    }

    float4 g4 = __ldg((const float4*)(lng + tx * 4));
    float4 b4 = __ldg((const float4*)(lnb + tx * 4));
#pragma unroll
    for (int rr = 0; rr < 8; rr++) {
        float s = v[rr][0] + v[rr][1] + v[rr][2] + v[rr][3];
        float q = v[rr][0] * v[rr][0] + v[rr][1] * v[rr][1] +
                  v[rr][2] * v[rr][2] + v[rr][3] * v[rr][3];
#pragma unroll
        for (int off = 16; off > 0; off >>= 1) {
            s += __shfl_xor_sync(0xffffffffu, s, off);
            q += __shfl_xor_sync(0xffffffffu, q, off);
        }
        const float mu = s * (1.0f / 128.0f);
        const float var = q * (1.0f / 128.0f) - mu * mu;
        const float rstd = rsqrtf(var + 1e-5f);
        const int node = nb + r0 + rr;
        if (node < NNODES) {
            float4 o;
            o.x = (v[rr][0] - mu) * rstd * g4.x + b4.x;
            o.y = (v[rr][1] - mu) * rstd * g4.y + b4.y;
            o.z = (v[rr][2] - mu) * rstd * g4.z + b4.z;
            o.w = (v[rr][3] - mu) * rstd * g4.w + b4.w;
            *(float4*)(out_h + (long long)node * Hdim + tx * 4) = o;
        }
    }
}

// ---------- launch ----------
extern "C" void kernel_launch(void* const* d_in, const int* in_sizes, int n_in,
                              void* d_out, int out_size) {
    const float* h   = (const float*)d_in[0];
    const float* x   = (const float*)d_in[1];
    const void*  ei  = d_in[2];
    const float* We1 = (const float*)d_in[3];
    const float* be1 = (const float*)d_in[4];
    const float* We2 = (const float*)d_in[5];
    const float* be2 = (const float*)d_in[6];
    const float* Wc1 = (const float*)d_in[7];
    const float* bc1 = (const float*)d_in[8];
    const float* Wc2 = (const float*)d_in[9];
    const float* Wn1 = (const float*)d_in[10];
    const float* bn1 = (const float*)d_in[11];
    const float* Wn2 = (const float*)d_in[12];
    const float* bn2 = (const float*)d_in[13];
    const float* lng = (const float*)d_in[14];
    const float* lnb = (const float*)d_in[15];

    float* out_h = (float*)d_out;
    float* out_x = out_h + (long long)NNODES * Hdim;

    const int SMEM_PREP = BUF128 * 4;
    const int SMEM_NODE = (BUF256 + BUF128) * 4;

    cudaFuncSetAttribute(prep_kernel, cudaFuncAttributeMaxDynamicSharedMemorySize, SMEM_PREP);
    cudaFuncSetAttribute(edge_mma_kernel, cudaFuncAttributeMaxDynamicSharedMemorySize, EB_TOTAL);
    cudaFuncSetAttribute(node_kernel, cudaFuncAttributeMaxDynamicSharedMemorySize, SMEM_NODE);

    detect_kernel<<<1, 32>>>((const int*)ei);
    init_kernel<<<((long long)NNODES * Hdim + 255) / 256, 256>>>(x, out_x);
    wsetup_kernel<<<32, 256>>>(We2, Wc1);
    prep_kernel<<<(NNODES + TILE - 1) / TILE, 256, SMEM_PREP>>>(h, We1, be1);
    edge_mma_kernel<<<NEDGES / ET, 256, EB_TOTAL>>>(x, ei, We1, be2, bc1, Wc2, out_x);
    node_kernel<<<(NNODES + TILE - 1) / TILE, 256, SMEM_NODE>>>(h, Wn1, bn1, Wn2, bn2,
                                                                lng, lnb, out_h);
}

// round 15
// speedup vs baseline: 1.7853x; 1.1201x over previous
#include <cuda_runtime.h>
#include <cuda_bf16.h>
#include <cstdint>

#define Hdim 128
#define NNODES 50000
#define NEDGES 800000
#define TILE 64
#define LDA 68
#define SWZ(f, e) ((f) * LDA + ((((((e) >> 2)) ^ (((f) >> 2) & 15)) << 2) | ((e) & 3)))
#define BUF128 (128 * LDA)
#define BUF256 (256 * LDA)

// ---- HMMA edge kernel ----
#define ET 64             // edges per CTA (16 per warp, 4 warps)
#define AROWB 272         // A-tile row pitch in bytes (68 words) -> conflict-free frags
#define EB_ROWI 0
#define EB_COLI 256
#define EB_D2S  512
#define EB_ND   768
#define EB_AHI  2048
#define EB_ALO  (EB_AHI + ET * AROWB)
#define EB_TOTAL (EB_ALO + ET * AROWB)

__device__ int   g_is64;
__device__ float g_mi[(long long)NNODES * Hdim];
__device__ float g_P [(long long)NNODES * Hdim];
__device__ float g_Q [(long long)NNODES * Hdim];
// W fragments: [0]=We2_hi [1]=We2_lo [2]=Wc1_hi [3]=Wc1_lo.
// Index: [(kt*16+nt)*32 + lane] -> uint2{b0,b1} per m16n8k16 B-fragment layout.
__device__ __align__(16) uint2 g_WF[4][4096];

// ---------- f32x2 helpers (prep/node FFMA path) ----------
__device__ __forceinline__ unsigned long long pk2(float lo, float hi) {
    unsigned long long r;
    asm("mov.b64 %0, {%1,%2};" : "=l"(r) : "f"(lo), "f"(hi));
    return r;
}
__device__ __forceinline__ void upk2(unsigned long long v, float& lo, float& hi) {
    asm("mov.b64 {%0,%1}, %2;" : "=f"(lo), "=f"(hi) : "l"(v));
}
#define FMA2(d, a, b) asm("fma.rn.f32x2 %0, %1, %2, %0;" : "+l"(d) : "l"(a), "l"(b))

__device__ __forceinline__ void red_add_v2(float* p, float a, float b) {
    asm volatile("red.global.add.v2.f32 [%0], {%1,%2};"
                 :: "l"(p), "f"(a), "f"(b) : "memory");
}
__device__ __forceinline__ float silu_f(float v) { return v / (1.0f + __expf(-v)); }

// hi/lo bf16 split: returns packed bf16x2 of (a,b) hi parts, residuals out.
__device__ __forceinline__ uint32_t split_hi(float a, float b, float& ra, float& rb) {
    __nv_bfloat162 h = __floats2bfloat162_rn(a, b);
    ra = a - __bfloat162float(h.x);
    rb = b - __bfloat162float(h.y);
    return *reinterpret_cast<uint32_t*>(&h);
}
__device__ __forceinline__ uint32_t pack_bf(float a, float b) {
    __nv_bfloat162 h = __floats2bfloat162_rn(a, b);
    return *reinterpret_cast<uint32_t*>(&h);
}

// ---------- mma.sync m16n8k16 bf16 (baseline PTX, runs on HMMA) ----------
__device__ __forceinline__ void mma16816(float d[4], const uint32_t a[4],
                                         uint32_t b0, uint32_t b1) {
    asm volatile(
        "mma.sync.aligned.m16n8k16.row.col.f32.bf16.bf16.f32 "
        "{%0,%1,%2,%3}, {%4,%5,%6,%7}, {%8,%9}, {%0,%1,%2,%3};"
        : "+f"(d[0]), "+f"(d[1]), "+f"(d[2]), "+f"(d[3])
        : "r"(a[0]), "r"(a[1]), "r"(a[2]), "r"(a[3]), "r"(b0), "r"(b1));
}

// ---------- prep/node GEMM tile (R10-proven FFMA) ----------
template <int K>
__device__ __forceinline__ void gemm_tile(const float* __restrict__ As,
                                          const float* __restrict__ W,
                                          const float* __restrict__ bias,
                                          unsigned long long acc[4][4],
                                          int tx, int r0) {
    const int Q = r0 >> 2;
    float4 b4 = bias ? __ldg((const float4*)(bias + tx * 4))
                     : make_float4(0.f, 0.f, 0.f, 0.f);
#pragma unroll
    for (int i = 0; i < 4; i++) {
        acc[i][0] = pk2(b4.x, b4.x);
        acc[i][1] = pk2(b4.y, b4.y);
        acc[i][2] = pk2(b4.z, b4.z);
        acc[i][3] = pk2(b4.w, b4.w);
    }
#pragma unroll 2
    for (int kg = 0; kg < K / 4; kg++) {
        const int s = kg & 15;
        const float* aP0 = As + (kg * 4) * LDA + ((Q ^ s) << 2);
        const float* aQ0 = As + (kg * 4) * LDA + (((Q + 1) ^ s) << 2);
        const float* Wp = W + (long long)(kg * 4) * Hdim + tx * 4;
#pragma unroll
        for (int kk = 0; kk < 4; kk++) {
            float4 w = __ldg((const float4*)(Wp + kk * Hdim));
            unsigned long long w0 = pk2(w.x, w.x);
            unsigned long long w1 = pk2(w.y, w.y);
            unsigned long long w2 = pk2(w.z, w.z);
            unsigned long long w3 = pk2(w.w, w.w);
            ulonglong2 aP = *(const ulonglong2*)(aP0 + kk * LDA);
            ulonglong2 aQ = *(const ulonglong2*)(aQ0 + kk * LDA);
            unsigned long long a2[4] = {aP.x, aP.y, aQ.x, aQ.y};
#pragma unroll
            for (int i = 0; i < 4; i++) {
                FMA2(acc[i][0], a2[i], w0);
                FMA2(acc[i][1], a2[i], w1);
                FMA2(acc[i][2], a2[i], w2);
                FMA2(acc[i][3], a2[i], w3);
            }
        }
    }
}

// ---------- index dtype detection ----------
__global__ void detect_kernel(const int* ei32) {
    if (blockIdx.x == 0 && threadIdx.x == 0) {
        int f = 1;
        for (int i = 0; i < 1024; i++) {
            if (ei32[2 * i + 1] != 0) { f = 0; break; }
        }
        g_is64 = f;
    }
}

// ---------- init ----------
__global__ void init_kernel(const float* __restrict__ x, float* __restrict__ out_x) {
    long long i = (long long)blockIdx.x * blockDim.x + threadIdx.x;
    if (i < (long long)NNODES * Hdim) g_mi[i] = 0.0f;
    if (i < (long long)NNODES * 3)    out_x[i] = x[i];
}

// ---------- prep: P/Q GEMMs + (blocks 0..31) weight fragment pre-pack ----------
// Fragment layout (m16n8k16 .col):
//   b0 = (W[16kt+2t][8nt+g], W[16kt+2t+1][8nt+g])
//   b1 = (W[16kt+2t+8][8nt+g], W[16kt+2t+9][8nt+g]),  g=lane>>2, t=lane&3.
__global__ void __launch_bounds__(256) prep_kernel(
    const float* __restrict__ h,
    const float* __restrict__ We1, const float* __restrict__ be1,
    const float* __restrict__ We2, const float* __restrict__ Wc1) {
    extern __shared__ float sm[];
    float* As = sm;

    const int tid = threadIdx.x;
    const int tx = tid & 31, ty = tid >> 5;
    const int r0 = ty * 8;
    const int nb = blockIdx.x * TILE;

    // fused wsetup: first 32 blocks pack W fragments (8192 items)
    {
        int id = blockIdx.x * 256 + tid;
        if (id < 8192) {
            int lane = id & 31, nt = (id >> 5) & 15, kt = (id >> 9) & 7, mat = id >> 12;
            int g = lane >> 2, t = lane & 3;
            const float* W = mat ? Wc1 : We2;
            int n = nt * 8 + g;
            float w00 = W[(kt * 16 + 2 * t + 0) * Hdim + n];
            float w01 = W[(kt * 16 + 2 * t + 1) * Hdim + n];
            float w10 = W[(kt * 16 + 2 * t + 8) * Hdim + n];
            float w11 = W[(kt * 16 + 2 * t + 9) * Hdim + n];
            float r00, r01, r10, r11;
            uint32_t h0 = split_hi(w00, w01, r00, r01);
            uint32_t h1 = split_hi(w10, w11, r10, r11);
            int idx = (kt * 16 + nt) * 32 + lane;
            g_WF[mat * 2 + 0][idx] = make_uint2(h0, h1);
            g_WF[mat * 2 + 1][idx] = make_uint2(pack_bf(r00, r01), pack_bf(r10, r11));
        }
    }

    for (int e = ty; e < TILE; e += 8) {
        const int node = nb + e;
        const int d0 = tx * 4;
        float4 hv = make_float4(0.f, 0.f, 0.f, 0.f);
        if (node < NNODES) hv = __ldg((const float4*)(h + (long long)node * Hdim + d0));
        As[SWZ(d0 + 0, e)] = hv.x;
        As[SWZ(d0 + 1, e)] = hv.y;
        As[SWZ(d0 + 2, e)] = hv.z;
        As[SWZ(d0 + 3, e)] = hv.w;
    }
    __syncthreads();

    unsigned long long acc[4][4];

    gemm_tile<128>(As, We1, be1, acc, tx, r0);
#pragma unroll
    for (int i = 0; i < 4; i++) {
        const int n0 = nb + r0 + 2 * i, n1 = n0 + 1;
        float4 oA, oB;
        float v0, v1;
        upk2(acc[i][0], v0, v1); oA.x = v0; oB.x = v1;
        upk2(acc[i][1], v0, v1); oA.y = v0; oB.y = v1;
        upk2(acc[i][2], v0, v1); oA.z = v0; oB.z = v1;
        upk2(acc[i][3], v0, v1); oA.w = v0; oB.w = v1;
        if (n0 < NNODES) *(float4*)(g_P + (long long)n0 * Hdim + tx * 4) = oA;
        if (n1 < NNODES) *(float4*)(g_P + (long long)n1 * Hdim + tx * 4) = oB;
    }

    gemm_tile<128>(As, We1 + 128 * Hdim, (const float*)0, acc, tx, r0);
#pragma unroll
    for (int i = 0; i < 4; i++) {
        const int n0 = nb + r0 + 2 * i, n1 = n0 + 1;
        float4 oA, oB;
        float v0, v1;
        upk2(acc[i][0], v0, v1); oA.x = v0; oB.x = v1;
        upk2(acc[i][1], v0, v1); oA.y = v0; oB.y = v1;
        upk2(acc[i][2], v0, v1); oA.z = v0; oB.z = v1;
        upk2(acc[i][3], v0, v1); oA.w = v0; oB.w = v1;
        if (n0 < NNODES) *(float4*)(g_Q + (long long)n0 * Hdim + tx * 4) = oA;
        if (n1 < NNODES) *(float4*)(g_Q + (long long)n1 * Hdim + tx * 4) = oB;
    }
}

// ---------- HMMA GEMM over the warp's 16-edge A tile: d[nt][4] += A @ W(frag) ----------
__device__ __forceinline__ void gemm_mma(const char* smc, const uint2* __restrict__ WFh,
                                         const uint2* __restrict__ WFl,
                                         float d[16][4], int e0, int lane) {
    const int g = lane >> 2, t = lane & 3;
#pragma unroll
    for (int nt = 0; nt < 16; nt++)
#pragma unroll
        for (int j = 0; j < 4; j++) d[nt][j] = 0.0f;
    const char* rowg = smc + EB_AHI + (e0 + g) * AROWB;
    const char* row8 = rowg + 8 * AROWB;
#pragma unroll 1
    for (int kt = 0; kt < 8; kt++) {
        const int kb = kt * 32 + t * 4;
        uint32_t ah[4], al[4];
        ah[0] = *(const uint32_t*)(rowg + kb);
        ah[1] = *(const uint32_t*)(row8 + kb);
        ah[2] = *(const uint32_t*)(rowg + kb + 16);
        ah[3] = *(const uint32_t*)(row8 + kb + 16);
        al[0] = *(const uint32_t*)(rowg + (EB_ALO - EB_AHI) + kb);
        al[1] = *(const uint32_t*)(row8 + (EB_ALO - EB_AHI) + kb);
        al[2] = *(const uint32_t*)(rowg + (EB_ALO - EB_AHI) + kb + 16);
        al[3] = *(const uint32_t*)(row8 + (EB_ALO - EB_AHI) + kb + 16);
        const uint2* fh = WFh + kt * 16 * 32 + lane;
        const uint2* fl = WFl + kt * 16 * 32 + lane;
#pragma unroll
        for (int nt = 0; nt < 16; nt++) {
            uint2 bh = __ldg(fh + nt * 32);
            uint2 bl = __ldg(fl + nt * 32);
            mma16816(d[nt], ah, bh.x, bh.y);
            mma16816(d[nt], ah, bl.x, bl.y);
            mma16816(d[nt], al, bh.x, bh.y);
        }
    }
}

// ---------- HMMA edge kernel: 64 edges/CTA (128 thr), warp-independent ----------
__global__ void __launch_bounds__(128) edge_mma_kernel(
    const float* __restrict__ x, const void* __restrict__ ei,
    const float* __restrict__ We1,
    const float* __restrict__ be2, const float* __restrict__ bc1,
    const float* __restrict__ Wc2,
    float* __restrict__ out_x) {
    extern __shared__ float sm[];
    char* smc = (char*)sm;
    int*   rowi = (int*)(smc + EB_ROWI);
    int*   coli = (int*)(smc + EB_COLI);
    float* d2s  = (float*)(smc + EB_D2S);
    float* nd   = (float*)(smc + EB_ND);

    const int tid = threadIdx.x, wid = tid >> 5, lane = tid & 31;
    const int g = lane >> 2, t = lane & 3;
    const int e0 = wid * 16;
    const int eb = blockIdx.x * ET;
    const int is64 = g_is64;

    // geometry (tid<64 covers 64 edges)
    if (tid < ET) {
        int e = tid;
        long long r, c;
        if (is64) {
            const long long* p = (const long long*)ei;
            r = p[eb + e]; c = p[NEDGES + eb + e];
        } else {
            const int* p = (const int*)ei;
            r = p[eb + e]; c = p[NEDGES + eb + e];
        }
        rowi[e] = (int)r; coli[e] = (int)c;
        float dx = __ldg(x + r * 3 + 0) - __ldg(x + c * 3 + 0);
        float dy = __ldg(x + r * 3 + 1) - __ldg(x + c * 3 + 1);
        float dz = __ldg(x + r * 3 + 2) - __ldg(x + c * 3 + 2);
        float d2 = dx * dx + dy * dy + dz * dz;
        float dist = sqrtf(d2);
        d2s[e] = d2;
        float inv = 1.0f / (dist + 1e-8f);
        nd[0 * ET + e] = dx * inv;
        nd[1 * ET + e] = dy * inv;
        nd[2 * ET + e] = dz * inv;
    }
    __syncthreads();

    // m1 gather for this warp's 16 edges; split hi/lo into A tiles
    {
        const int k0 = lane * 4;
        float4 w1c = __ldg((const float4*)(We1 + 256 * Hdim + k0));
#pragma unroll 2
        for (int e = 0; e < 16; e++) {
            const int er = e0 + e;
            const long long rr = rowi[er], cc = coli[er];
            float4 p = __ldg((const float4*)(g_P + rr * Hdim + k0));
            float4 q = __ldg((const float4*)(g_Q + cc * Hdim + k0));
            const float d2 = d2s[er];
            float m0 = silu_f(fmaf(d2, w1c.x, p.x + q.x));
            float m1 = silu_f(fmaf(d2, w1c.y, p.y + q.y));
            float m2 = silu_f(fmaf(d2, w1c.z, p.z + q.z));
            float m3 = silu_f(fmaf(d2, w1c.w, p.w + q.w));
            float r0, r1, r2, r3;
            uint32_t h01 = split_hi(m0, m1, r0, r1);
            uint32_t h23 = split_hi(m2, m3, r2, r3);
            *(uint2*)(smc + EB_AHI + er * AROWB + lane * 8) = make_uint2(h01, h23);
            *(uint2*)(smc + EB_ALO + er * AROWB + lane * 8) =
                make_uint2(pack_bf(r0, r1), pack_bf(r2, r3));
        }
    }
    __syncwarp();

    float d[16][4];

    // GEMM1: D = m1 @ We2
    gemm_mma(smc, g_WF[0], g_WF[1], d, e0, lane);

    // epilogue1: m_ij = silu(D + be2); red_add to g_mi; re-split into A tiles
    {
        const long long rg = (long long)rowi[e0 + g] * Hdim;
        const long long r8 = (long long)rowi[e0 + g + 8] * Hdim;
#pragma unroll
        for (int nt = 0; nt < 16; nt++) {
            const int c0 = nt * 8 + 2 * t;
            float2 b2 = __ldg((const float2*)(be2 + c0));
            float m00 = silu_f(d[nt][0] + b2.x);
            float m01 = silu_f(d[nt][1] + b2.y);
            float m10 = silu_f(d[nt][2] + b2.x);
            float m11 = silu_f(d[nt][3] + b2.y);
            red_add_v2(g_mi + rg + c0, m00, m01);
            red_add_v2(g_mi + r8 + c0, m10, m11);
            float q0, q1, q2, q3;
            uint32_t h0 = split_hi(m00, m01, q0, q1);
            uint32_t h1 = split_hi(m10, m11, q2, q3);
            const int og = (e0 + g) * AROWB + c0 * 2;
            const int o8 = (e0 + g + 8) * AROWB + c0 * 2;
            *(uint32_t*)(smc + EB_AHI + og) = h0;
            *(uint32_t*)(smc + EB_AHI + o8) = h1;
            *(uint32_t*)(smc + EB_ALO + og) = pack_bf(q0, q1);
            *(uint32_t*)(smc + EB_ALO + o8) = pack_bf(q2, q3);
        }
    }
    __syncwarp();

    // GEMM2: D = m_ij @ Wc1
    gemm_mma(smc, g_WF[2], g_WF[3], d, e0, lane);

    // epilogue2: s = tanh(silu(D + bc1) . Wc2) * 0.1; force scatter
    {
        float sl = 0.0f, sh = 0.0f;
#pragma unroll
        for (int nt = 0; nt < 16; nt++) {
            const int c0 = nt * 8 + 2 * t;
            float2 bb = __ldg((const float2*)(bc1 + c0));
            float2 wc = __ldg((const float2*)(Wc2 + c0));
            sl = fmaf(silu_f(d[nt][0] + bb.x), wc.x, sl);
            sl = fmaf(silu_f(d[nt][1] + bb.y), wc.y, sl);
            sh = fmaf(silu_f(d[nt][2] + bb.x), wc.x, sh);
            sh = fmaf(silu_f(d[nt][3] + bb.y), wc.y, sh);
        }
        sl += __shfl_xor_sync(0xffffffffu, sl, 1);
        sl += __shfl_xor_sync(0xffffffffu, sl, 2);
        sh += __shfl_xor_sync(0xffffffffu, sh, 1);
        sh += __shfl_xor_sync(0xffffffffu, sh, 2);
        if (t == 0) {
            const int eg = e0 + g, e8 = e0 + g + 8;
            const float s0 = tanhf(sl) * 0.1f;
            const float s1 = tanhf(sh) * 0.1f;
            float* p0 = out_x + (long long)rowi[eg] * 3;
            float* p1 = out_x + (long long)rowi[e8] * 3;
            atomicAdd(p0 + 0, nd[0 * ET + eg] * s0);
            atomicAdd(p0 + 1, nd[1 * ET + eg] * s0);
            atomicAdd(p0 + 2, nd[2 * ET + eg] * s0);
            atomicAdd(p1 + 0, nd[0 * ET + e8] * s1);
            atomicAdd(p1 + 1, nd[1 * ET + e8] * s1);
            atomicAdd(p1 + 2, nd[2 * ET + e8] * s1);
        }
    }
}

// ---------- node kernel (R10-proven) ----------
__global__ void __launch_bounds__(256, 2) node_kernel(
    const float* __restrict__ h,
    const float* __restrict__ Wn1, const float* __restrict__ bn1,
    const float* __restrict__ Wn2, const float* __restrict__ bn2,
    const float* __restrict__ lng, const float* __restrict__ lnb,
    float* __restrict__ out_h) {
    extern __shared__ float sm[];
    float* As = sm;
    float* Bs = As + BUF256;

    const int tid = threadIdx.x;
    const int tx = tid & 31, ty = tid >> 5;
    const int r0 = ty * 8;
    const int nb = blockIdx.x * TILE;

    for (int e = ty; e < TILE; e += 8) {
        const int node = nb + e;
        const int d0 = tx * 4;
        if (node < NNODES) {
            float4 hv = __ldg((const float4*)(h + (long long)node * Hdim + d0));
            As[SWZ(d0 + 0, e)] = hv.x;
            As[SWZ(d0 + 1, e)] = hv.y;
            As[SWZ(d0 + 2, e)] = hv.z;
            As[SWZ(d0 + 3, e)] = hv.w;
            float4 mv = *(const float4*)(g_mi + (long long)node * Hdim + d0);
            As[SWZ(Hdim + d0 + 0, e)] = mv.x;
            As[SWZ(Hdim + d0 + 1, e)] = mv.y;
            As[SWZ(Hdim + d0 + 2, e)] = mv.z;
            As[SWZ(Hdim + d0 + 3, e)] = mv.w;
        } else {
#pragma unroll
            for (int q = 0; q < 4; q++) {
                As[SWZ(d0 + q, e)] = 0.0f;
                As[SWZ(Hdim + d0 + q, e)] = 0.0f;
            }
        }
    }
    __syncthreads();

    unsigned long long acc[4][4];
    gemm_tile<256>(As, Wn1, bn1, acc, tx, r0);
#pragma unroll
    for (int i = 0; i < 4; i++) {
#pragma unroll
        for (int j = 0; j < 4; j++) {
            float v0, v1; upk2(acc[i][j], v0, v1);
            *(unsigned long long*)(Bs + SWZ(tx * 4 + j, r0 + 2 * i)) =
                pk2(silu_f(v0), silu_f(v1));
        }
    }
    __syncthreads();

    gemm_tile<128>(Bs, Wn2, bn2, acc, tx, r0);

    float v[8][4];
#pragma unroll
    for (int i = 0; i < 4; i++) {
        const int n0 = nb + r0 + 2 * i, n1 = n0 + 1;
        float4 hA = make_float4(0.f, 0.f, 0.f, 0.f);
        float4 hB = make_float4(0.f, 0.f, 0.f, 0.f);
        if (n0 < NNODES) hA = __ldg((const float4*)(h + (long long)n0 * Hdim + tx * 4));
        if (n1 < NNODES) hB = __ldg((const float4*)(h + (long long)n1 * Hdim + tx * 4));
        float v0, v1;
        upk2(acc[i][0], v0, v1); v[2 * i][0] = v0 + hA.x; v[2 * i + 1][0] = v1 + hB.x;
        upk2(acc[i][1], v0, v1); v[2 * i][1] = v0 + hA.y; v[2 * i + 1][1] = v1 + hB.y;
        upk2(acc[i][2], v0, v1); v[2 * i][2] = v0 + hA.z; v[2 * i + 1][2] = v1 + hB.z;
        upk2(acc[i][3], v0, v1); v[2 * i][3] = v0 + hA.w; v[2 * i + 1][3] = v1 + hB.w;
    }

    float4 g4 = __ldg((const float4*)(lng + tx * 4));
    float4 b4 = __ldg((const float4*)(lnb + tx * 4));
#pragma unroll
    for (int rr = 0; rr < 8; rr++) {
        float s = v[rr][0] + v[rr][1] + v[rr][2] + v[rr][3];
        float q = v[rr][0] * v[rr][0] + v[rr][1] * v[rr][1] +
                  v[rr][2] * v[rr][2] + v[rr][3] * v[rr][3];
#pragma unroll
        for (int off = 16; off > 0; off >>= 1) {
            s += __shfl_xor_sync(0xffffffffu, s, off);
            q += __shfl_xor_sync(0xffffffffu, q, off);
        }
        const float mu = s * (1.0f / 128.0f);
        const float var = q * (1.0f / 128.0f) - mu * mu;
        const float rstd = rsqrtf(var + 1e-5f);
        const int node = nb + r0 + rr;
        if (node < NNODES) {
            float4 o;
            o.x = (v[rr][0] - mu) * rstd * g4.x + b4.x;
            o.y = (v[rr][1] - mu) * rstd * g4.y + b4.y;
            o.z = (v[rr][2] - mu) * rstd * g4.z + b4.z;
            o.w = (v[rr][3] - mu) * rstd * g4.w + b4.w;
            *(float4*)(out_h + (long long)node * Hdim + tx * 4) = o;
        }
    }
}

// ---------- launch ----------
extern "C" void kernel_launch(void* const* d_in, const int* in_sizes, int n_in,
                              void* d_out, int out_size) {
    const float* h   = (const float*)d_in[0];
    const float* x   = (const float*)d_in[1];
    const void*  ei  = d_in[2];
    const float* We1 = (const float*)d_in[3];
    const float* be1 = (const float*)d_in[4];
    const float* We2 = (const float*)d_in[5];
    const float* be2 = (const float*)d_in[6];
    const float* Wc1 = (const float*)d_in[7];
    const float* bc1 = (const float*)d_in[8];
    const float* Wc2 = (const float*)d_in[9];
    const float* Wn1 = (const float*)d_in[10];
    const float* bn1 = (const float*)d_in[11];
    const float* Wn2 = (const float*)d_in[12];
    const float* bn2 = (const float*)d_in[13];
    const float* lng = (const float*)d_in[14];
    const float* lnb = (const float*)d_in[15];

    float* out_h = (float*)d_out;
    float* out_x = out_h + (long long)NNODES * Hdim;

    const int SMEM_PREP = BUF128 * 4;
    const int SMEM_NODE = (BUF256 + BUF128) * 4;

    cudaFuncSetAttribute(prep_kernel, cudaFuncAttributeMaxDynamicSharedMemorySize, SMEM_PREP);
    cudaFuncSetAttribute(edge_mma_kernel, cudaFuncAttributeMaxDynamicSharedMemorySize, EB_TOTAL);
    cudaFuncSetAttribute(node_kernel, cudaFuncAttributeMaxDynamicSharedMemorySize, SMEM_NODE);

    detect_kernel<<<1, 32>>>((const int*)ei);
    init_kernel<<<((long long)NNODES * Hdim + 255) / 256, 256>>>(x, out_x);
    prep_kernel<<<(NNODES + TILE - 1) / TILE, 256, SMEM_PREP>>>(h, We1, be1, We2, Wc1);
    edge_mma_kernel<<<NEDGES / ET, 128, EB_TOTAL>>>(x, ei, We1, be2, bc1, Wc2, out_x);
    node_kernel<<<(NNODES + TILE - 1) / TILE, 256, SMEM_NODE>>>(h, Wn1, bn1, Wn2, bn2,
                                                                lng, lnb, out_h);
}

// round 16
// speedup vs baseline: 1.8172x; 1.0179x over previous
#include <cuda_runtime.h>
#include <cuda_bf16.h>
#include <cstdint>

#define Hdim 128
#define NNODES 50000
#define NEDGES 800000
#define TILE 64
#define LDA 68
#define SWZ(f, e) ((f) * LDA + ((((((e) >> 2)) ^ (((f) >> 2) & 15)) << 2) | ((e) & 3)))
#define BUF128 (128 * LDA)
#define BUF256 (256 * LDA)

// ---- HMMA edge kernel ----
#define ET 64             // edges per CTA (16 per warp, 4 warps)
#define AROWB 272         // A-tile row pitch in bytes -> conflict-free frags
#define EB_ROWI 0
#define EB_COLI 256
#define EB_D2S  512
#define EB_ND   768
#define EB_AHI  2048
#define EB_ALO  (EB_AHI + ET * AROWB)
#define EB_TOTAL (EB_ALO + ET * AROWB)

__device__ int   g_is64;
__device__ float g_mi[(long long)NNODES * Hdim];
__device__ float g_P [(long long)NNODES * Hdim];
__device__ float g_Q [(long long)NNODES * Hdim];
// W fragments: [0]=We2_hi [1]=We2_lo [2]=Wc1_hi [3]=Wc1_lo.
// Index: [(kt*16+nt)*32 + lane] -> uint2{b0,b1} per m16n8k16 B-fragment layout.
__device__ __align__(16) uint2 g_WF[4][4096];

// ---------- f32x2 helpers (prep/node FFMA path) ----------
__device__ __forceinline__ unsigned long long pk2(float lo, float hi) {
    unsigned long long r;
    asm("mov.b64 %0, {%1,%2};" : "=l"(r) : "f"(lo), "f"(hi));
    return r;
}
__device__ __forceinline__ void upk2(unsigned long long v, float& lo, float& hi) {
    asm("mov.b64 {%0,%1}, %2;" : "=f"(lo), "=f"(hi) : "l"(v));
}
#define FMA2(d, a, b) asm("fma.rn.f32x2 %0, %1, %2, %0;" : "+l"(d) : "l"(a), "l"(b))

__device__ __forceinline__ void red_add_v2(float* p, float a, float b) {
    asm volatile("red.global.add.v2.f32 [%0], {%1,%2};"
                 :: "l"(p), "f"(a), "f"(b) : "memory");
}
__device__ __forceinline__ float silu_f(float v) { return v / (1.0f + __expf(-v)); }

__device__ __forceinline__ uint32_t split_hi(float a, float b, float& ra, float& rb) {
    __nv_bfloat162 h = __floats2bfloat162_rn(a, b);
    ra = a - __bfloat162float(h.x);
    rb = b - __bfloat162float(h.y);
    return *reinterpret_cast<uint32_t*>(&h);
}
__device__ __forceinline__ uint32_t pack_bf(float a, float b) {
    __nv_bfloat162 h = __floats2bfloat162_rn(a, b);
    return *reinterpret_cast<uint32_t*>(&h);
}

// ---------- mma.sync m16n8k16 bf16 (baseline PTX, runs on HMMA) ----------
__device__ __forceinline__ void mma16816(float d[4], const uint32_t a[4],
                                         uint32_t b0, uint32_t b1) {
    asm volatile(
        "mma.sync.aligned.m16n8k16.row.col.f32.bf16.bf16.f32 "
        "{%0,%1,%2,%3}, {%4,%5,%6,%7}, {%8,%9}, {%0,%1,%2,%3};"
        : "+f"(d[0]), "+f"(d[1]), "+f"(d[2]), "+f"(d[3])
        : "r"(a[0]), "r"(a[1]), "r"(a[2]), "r"(a[3]), "r"(b0), "r"(b1));
}

// ---------- prep/node GEMM tile (R10-proven FFMA) ----------
template <int K>
__device__ __forceinline__ void gemm_tile(const float* __restrict__ As,
                                          const float* __restrict__ W,
                                          const float* __restrict__ bias,
                                          unsigned long long acc[4][4],
                                          int tx, int r0) {
    const int Q = r0 >> 2;
    float4 b4 = bias ? __ldg((const float4*)(bias + tx * 4))
                     : make_float4(0.f, 0.f, 0.f, 0.f);
#pragma unroll
    for (int i = 0; i < 4; i++) {
        acc[i][0] = pk2(b4.x, b4.x);
        acc[i][1] = pk2(b4.y, b4.y);
        acc[i][2] = pk2(b4.z, b4.z);
        acc[i][3] = pk2(b4.w, b4.w);
    }
#pragma unroll 2
    for (int kg = 0; kg < K / 4; kg++) {
        const int s = kg & 15;
        const float* aP0 = As + (kg * 4) * LDA + ((Q ^ s) << 2);
        const float* aQ0 = As + (kg * 4) * LDA + (((Q + 1) ^ s) << 2);
        const float* Wp = W + (long long)(kg * 4) * Hdim + tx * 4;
#pragma unroll
        for (int kk = 0; kk < 4; kk++) {
            float4 w = __ldg((const float4*)(Wp + kk * Hdim));
            unsigned long long w0 = pk2(w.x, w.x);
            unsigned long long w1 = pk2(w.y, w.y);
            unsigned long long w2 = pk2(w.z, w.z);
            unsigned long long w3 = pk2(w.w, w.w);
            ulonglong2 aP = *(const ulonglong2*)(aP0 + kk * LDA);
            ulonglong2 aQ = *(const ulonglong2*)(aQ0 + kk * LDA);
            unsigned long long a2[4] = {aP.x, aP.y, aQ.x, aQ.y};
#pragma unroll
            for (int i = 0; i < 4; i++) {
                FMA2(acc[i][0], a2[i], w0);
                FMA2(acc[i][1], a2[i], w1);
                FMA2(acc[i][2], a2[i], w2);
                FMA2(acc[i][3], a2[i], w3);
            }
        }
    }
}

// ---------- index dtype detection ----------
__global__ void detect_kernel(const int* ei32) {
    if (blockIdx.x == 0 && threadIdx.x == 0) {
        int f = 1;
        for (int i = 0; i < 1024; i++) {
            if (ei32[2 * i + 1] != 0) { f = 0; break; }
        }
        g_is64 = f;
    }
}

// ---------- init ----------
__global__ void init_kernel(const float* __restrict__ x, float* __restrict__ out_x) {
    long long i = (long long)blockIdx.x * blockDim.x + threadIdx.x;
    if (i < (long long)NNODES * Hdim) g_mi[i] = 0.0f;
    if (i < (long long)NNODES * 3)    out_x[i] = x[i];
}

// ---------- prep: P/Q GEMMs + (blocks 0..31) weight fragment pre-pack ----------
__global__ void __launch_bounds__(256) prep_kernel(
    const float* __restrict__ h,
    const float* __restrict__ We1, const float* __restrict__ be1,
    const float* __restrict__ We2, const float* __restrict__ Wc1) {
    extern __shared__ float sm[];
    float* As = sm;

    const int tid = threadIdx.x;
    const int tx = tid & 31, ty = tid >> 5;
    const int r0 = ty * 8;
    const int nb = blockIdx.x * TILE;

    // fused wsetup: first 32 blocks pack W fragments (8192 items)
    {
        int id = blockIdx.x * 256 + tid;
        if (id < 8192) {
            int lane = id & 31, nt = (id >> 5) & 15, kt = (id >> 9) & 7, mat = id >> 12;
            int g = lane >> 2, t = lane & 3;
            const float* W = mat ? Wc1 : We2;
            int n = nt * 8 + g;
            float w00 = W[(kt * 16 + 2 * t + 0) * Hdim + n];
            float w01 = W[(kt * 16 + 2 * t + 1) * Hdim + n];
            float w10 = W[(kt * 16 + 2 * t + 8) * Hdim + n];
            float w11 = W[(kt * 16 + 2 * t + 9) * Hdim + n];
            float r00, r01, r10, r11;
            uint32_t h0 = split_hi(w00, w01, r00, r01);
            uint32_t h1 = split_hi(w10, w11, r10, r11);
            int idx = (kt * 16 + nt) * 32 + lane;
            g_WF[mat * 2 + 0][idx] = make_uint2(h0, h1);
            g_WF[mat * 2 + 1][idx] = make_uint2(pack_bf(r00, r01), pack_bf(r10, r11));
        }
    }

    for (int e = ty; e < TILE; e += 8) {
        const int node = nb + e;
        const int d0 = tx * 4;
        float4 hv = make_float4(0.f, 0.f, 0.f, 0.f);
        if (node < NNODES) hv = __ldg((const float4*)(h + (long long)node * Hdim + d0));
        As[SWZ(d0 + 0, e)] = hv.x;
        As[SWZ(d0 + 1, e)] = hv.y;
        As[SWZ(d0 + 2, e)] = hv.z;
        As[SWZ(d0 + 3, e)] = hv.w;
    }
    __syncthreads();

    unsigned long long acc[4][4];

    gemm_tile<128>(As, We1, be1, acc, tx, r0);
#pragma unroll
    for (int i = 0; i < 4; i++) {
        const int n0 = nb + r0 + 2 * i, n1 = n0 + 1;
        float4 oA, oB;
        float v0, v1;
        upk2(acc[i][0], v0, v1); oA.x = v0; oB.x = v1;
        upk2(acc[i][1], v0, v1); oA.y = v0; oB.y = v1;
        upk2(acc[i][2], v0, v1); oA.z = v0; oB.z = v1;
        upk2(acc[i][3], v0, v1); oA.w = v0; oB.w = v1;
        if (n0 < NNODES) *(float4*)(g_P + (long long)n0 * Hdim + tx * 4) = oA;
        if (n1 < NNODES) *(float4*)(g_P + (long long)n1 * Hdim + tx * 4) = oB;
    }

    gemm_tile<128>(As, We1 + 128 * Hdim, (const float*)0, acc, tx, r0);
#pragma unroll
    for (int i = 0; i < 4; i++) {
        const int n0 = nb + r0 + 2 * i, n1 = n0 + 1;
        float4 oA, oB;
        float v0, v1;
        upk2(acc[i][0], v0, v1); oA.x = v0; oB.x = v1;
        upk2(acc[i][1], v0, v1); oA.y = v0; oB.y = v1;
        upk2(acc[i][2], v0, v1); oA.z = v0; oB.z = v1;
        upk2(acc[i][3], v0, v1); oA.w = v0; oB.w = v1;
        if (n0 < NNODES) *(float4*)(g_Q + (long long)n0 * Hdim + tx * 4) = oA;
        if (n1 < NNODES) *(float4*)(g_Q + (long long)n1 * Hdim + tx * 4) = oB;
    }
}

// ---------- HMMA GEMM, pass-interleaved: 8 independent accumulator chains ----------
__device__ __forceinline__ void gemm_mma(const char* smc, const uint2* __restrict__ WFh,
                                         const uint2* __restrict__ WFl,
                                         float d[16][4], int e0, int lane) {
    const int g = lane >> 2, t = lane & 3;
#pragma unroll
    for (int nt = 0; nt < 16; nt++)
#pragma unroll
        for (int j = 0; j < 4; j++) d[nt][j] = 0.0f;
    const char* rowg = smc + EB_AHI + (e0 + g) * AROWB;
    const char* row8 = rowg + 8 * AROWB;
#pragma unroll 1
    for (int kt = 0; kt < 8; kt++) {
        const int kb = kt * 32 + t * 4;
        uint32_t ah[4], al[4];
        ah[0] = *(const uint32_t*)(rowg + kb);
        ah[1] = *(const uint32_t*)(row8 + kb);
        ah[2] = *(const uint32_t*)(rowg + kb + 16);
        ah[3] = *(const uint32_t*)(row8 + kb + 16);
        al[0] = *(const uint32_t*)(rowg + (EB_ALO - EB_AHI) + kb);
        al[1] = *(const uint32_t*)(row8 + (EB_ALO - EB_AHI) + kb);
        al[2] = *(const uint32_t*)(rowg + (EB_ALO - EB_AHI) + kb + 16);
        al[3] = *(const uint32_t*)(row8 + (EB_ALO - EB_AHI) + kb + 16);
        const uint2* fh = WFh + kt * 16 * 32 + lane;
        const uint2* fl = WFl + kt * 16 * 32 + lane;
#pragma unroll
        for (int ng = 0; ng < 2; ng++) {
            uint2 bh[8], bl[8];
#pragma unroll
            for (int j = 0; j < 8; j++) {
                bh[j] = __ldg(fh + (ng * 8 + j) * 32);
                bl[j] = __ldg(fl + (ng * 8 + j) * 32);
            }
            float (*dd)[4] = d + ng * 8;
#pragma unroll
            for (int j = 0; j < 8; j++) mma16816(dd[j], ah, bh[j].x, bh[j].y);
#pragma unroll
            for (int j = 0; j < 8; j++) mma16816(dd[j], ah, bl[j].x, bl[j].y);
#pragma unroll
            for (int j = 0; j < 8; j++) mma16816(dd[j], al, bh[j].x, bh[j].y);
        }
    }
}

// ---------- HMMA edge kernel: 64 edges/CTA (128 thr), warp-independent ----------
__global__ void __launch_bounds__(128) edge_mma_kernel(
    const float* __restrict__ x, const void* __restrict__ ei,
    const float* __restrict__ We1,
    const float* __restrict__ be2, const float* __restrict__ bc1,
    const float* __restrict__ Wc2,
    float* __restrict__ out_x) {
    extern __shared__ float sm[];
    char* smc = (char*)sm;
    int*   rowi = (int*)(smc + EB_ROWI);
    int*   coli = (int*)(smc + EB_COLI);
    float* d2s  = (float*)(smc + EB_D2S);
    float* nd   = (float*)(smc + EB_ND);

    const int tid = threadIdx.x, wid = tid >> 5, lane = tid & 31;
    const int g = lane >> 2, t = lane & 3;
    const int e0 = wid * 16;
    const int eb = blockIdx.x * ET;
    const int is64 = g_is64;

    if (tid < ET) {
        int e = tid;
        long long r, c;
        if (is64) {
            const long long* p = (const long long*)ei;
            r = p[eb + e]; c = p[NEDGES + eb + e];
        } else {
            const int* p = (const int*)ei;
            r = p[eb + e]; c = p[NEDGES + eb + e];
        }
        rowi[e] = (int)r; coli[e] = (int)c;
        float dx = __ldg(x + r * 3 + 0) - __ldg(x + c * 3 + 0);
        float dy = __ldg(x + r * 3 + 1) - __ldg(x + c * 3 + 1);
        float dz = __ldg(x + r * 3 + 2) - __ldg(x + c * 3 + 2);
        float d2 = dx * dx + dy * dy + dz * dz;
        float dist = sqrtf(d2);
        d2s[e] = d2;
        float inv = 1.0f / (dist + 1e-8f);
        nd[0 * ET + e] = dx * inv;
        nd[1 * ET + e] = dy * inv;
        nd[2 * ET + e] = dz * inv;
    }
    __syncthreads();

    // m1 gather for this warp's 16 edges; split hi/lo into A tiles
    {
        const int k0 = lane * 4;
        float4 w1c = __ldg((const float4*)(We1 + 256 * Hdim + k0));
#pragma unroll 2
        for (int e = 0; e < 16; e++) {
            const int er = e0 + e;
            const long long rr = rowi[er], cc = coli[er];
            float4 p = __ldg((const float4*)(g_P + rr * Hdim + k0));
            float4 q = __ldg((const float4*)(g_Q + cc * Hdim + k0));
            const float d2 = d2s[er];
            float m0 = silu_f(fmaf(d2, w1c.x, p.x + q.x));
            float m1 = silu_f(fmaf(d2, w1c.y, p.y + q.y));
            float m2 = silu_f(fmaf(d2, w1c.z, p.z + q.z));
            float m3 = silu_f(fmaf(d2, w1c.w, p.w + q.w));
            float r0, r1, r2, r3;
            uint32_t h01 = split_hi(m0, m1, r0, r1);
            uint32_t h23 = split_hi(m2, m3, r2, r3);
            *(uint2*)(smc + EB_AHI + er * AROWB + lane * 8) = make_uint2(h01, h23);
            *(uint2*)(smc + EB_ALO + er * AROWB + lane * 8) =
                make_uint2(pack_bf(r0, r1), pack_bf(r2, r3));
        }
    }
    __syncwarp();

    float d[16][4];

    // GEMM1: D = m1 @ We2
    gemm_mma(smc, g_WF[0], g_WF[1], d, e0, lane);

    // epilogue1: m_ij = silu(D + be2); red_add to g_mi; re-split into A tiles
    {
        const long long rg = (long long)rowi[e0 + g] * Hdim;
        const long long r8 = (long long)rowi[e0 + g + 8] * Hdim;
#pragma unroll
        for (int nt = 0; nt < 16; nt++) {
            const int c0 = nt * 8 + 2 * t;
            float2 b2 = __ldg((const float2*)(be2 + c0));
            float m00 = silu_f(d[nt][0] + b2.x);
            float m01 = silu_f(d[nt][1] + b2.y);
            float m10 = silu_f(d[nt][2] + b2.x);
            float m11 = silu_f(d[nt][3] + b2.y);
            red_add_v2(g_mi + rg + c0, m00, m01);
            red_add_v2(g_mi + r8 + c0, m10, m11);
            float q0, q1, q2, q3;
            uint32_t h0 = split_hi(m00, m01, q0, q1);
            uint32_t h1 = split_hi(m10, m11, q2, q3);
            const int og = (e0 + g) * AROWB + c0 * 2;
            const int o8 = (e0 + g + 8) * AROWB + c0 * 2;
            *(uint32_t*)(smc + EB_AHI + og) = h0;
            *(uint32_t*)(smc + EB_AHI + o8) = h1;
            *(uint32_t*)(smc + EB_ALO + og) = pack_bf(q0, q1);
            *(uint32_t*)(smc + EB_ALO + o8) = pack_bf(q2, q3);
        }
    }
    __syncwarp();

    // GEMM2: D = m_ij @ Wc1
    gemm_mma(smc, g_WF[2], g_WF[3], d, e0, lane);

    // epilogue2: s = tanh(silu(D + bc1) . Wc2) * 0.1; force scatter
    {
        float sl = 0.0f, sh = 0.0f;
#pragma unroll
        for (int nt = 0; nt < 16; nt++) {
            const int c0 = nt * 8 + 2 * t;
            float2 bb = __ldg((const float2*)(bc1 + c0));
            float2 wc = __ldg((const float2*)(Wc2 + c0));
            sl = fmaf(silu_f(d[nt][0] + bb.x), wc.x, sl);
            sl = fmaf(silu_f(d[nt][1] + bb.y), wc.y, sl);
            sh = fmaf(silu_f(d[nt][2] + bb.x), wc.x, sh);
            sh = fmaf(silu_f(d[nt][3] + bb.y), wc.y, sh);
        }
        sl += __shfl_xor_sync(0xffffffffu, sl, 1);
        sl += __shfl_xor_sync(0xffffffffu, sl, 2);
        sh += __shfl_xor_sync(0xffffffffu, sh, 1);
        sh += __shfl_xor_sync(0xffffffffu, sh, 2);
        if (t == 0) {
            const int eg = e0 + g, e8 = e0 + g + 8;
            const float s0 = tanhf(sl) * 0.1f;
            const float s1 = tanhf(sh) * 0.1f;
            float* p0 = out_x + (long long)rowi[eg] * 3;
            float* p1 = out_x + (long long)rowi[e8] * 3;
            atomicAdd(p0 + 0, nd[0 * ET + eg] * s0);
            atomicAdd(p0 + 1, nd[1 * ET + eg] * s0);
            atomicAdd(p0 + 2, nd[2 * ET + eg] * s0);
            atomicAdd(p1 + 0, nd[0 * ET + e8] * s1);
            atomicAdd(p1 + 1, nd[1 * ET + e8] * s1);
            atomicAdd(p1 + 2, nd[2 * ET + e8] * s1);
        }
    }
}

// ---------- node kernel (R10-proven) ----------
__global__ void __launch_bounds__(256, 2) node_kernel(
    const float* __restrict__ h,
    const float* __restrict__ Wn1, const float* __restrict__ bn1,
    const float* __restrict__ Wn2, const float* __restrict__ bn2,
    const float* __restrict__ lng, const float* __restrict__ lnb,
    float* __restrict__ out_h) {
    extern __shared__ float sm[];
    float* As = sm;
    float* Bs = As + BUF256;

    const int tid = threadIdx.x;
    const int tx = tid & 31, ty = tid >> 5;
    const int r0 = ty * 8;
    const int nb = blockIdx.x * TILE;

    for (int e = ty; e < TILE; e += 8) {
        const int node = nb + e;
        const int d0 = tx * 4;
        if (node < NNODES) {
            float4 hv = __ldg((const float4*)(h + (long long)node * Hdim + d0));
            As[SWZ(d0 + 0, e)] = hv.x;
            As[SWZ(d0 + 1, e)] = hv.y;
            As[SWZ(d0 + 2, e)] = hv.z;
            As[SWZ(d0 + 3, e)] = hv.w;
            float4 mv = *(const float4*)(g_mi + (long long)node * Hdim + d0);
            As[SWZ(Hdim + d0 + 0, e)] = mv.x;
            As[SWZ(Hdim + d0 + 1, e)] = mv.y;
            As[SWZ(Hdim + d0 + 2, e)] = mv.z;
            As[SWZ(Hdim + d0 + 3, e)] = mv.w;
        } else {
#pragma unroll
            for (int q = 0; q < 4; q++) {
                As[SWZ(d0 + q, e)] = 0.0f;
                As[SWZ(Hdim + d0 + q, e)] = 0.0f;
            }
        }
    }
    __syncthreads();

    unsigned long long acc[4][4];
    gemm_tile<256>(As, Wn1, bn1, acc, tx, r0);
#pragma unroll
    for (int i = 0; i < 4; i++) {
#pragma unroll
        for (int j = 0; j < 4; j++) {
            float v0, v1; upk2(acc[i][j], v0, v1);
            *(unsigned long long*)(Bs + SWZ(tx * 4 + j, r0 + 2 * i)) =
                pk2(silu_f(v0), silu_f(v1));
        }
    }
    __syncthreads();

    gemm_tile<128>(Bs, Wn2, bn2, acc, tx, r0);

    float v[8][4];
#pragma unroll
    for (int i = 0; i < 4; i++) {
        const int n0 = nb + r0 + 2 * i, n1 = n0 + 1;
        float4 hA = make_float4(0.f, 0.f, 0.f, 0.f);
        float4 hB = make_float4(0.f, 0.f, 0.f, 0.f);
        if (n0 < NNODES) hA = __ldg((const float4*)(h + (long long)n0 * Hdim + tx * 4));
        if (n1 < NNODES) hB = __ldg((const float4*)(h + (long long)n1 * Hdim + tx * 4));
        float v0, v1;
        upk2(acc[i][0], v0, v1); v[2 * i][0] = v0 + hA.x; v[2 * i + 1][0] = v1 + hB.x;
        upk2(acc[i][1], v0, v1); v[2 * i][1] = v0 + hA.y; v[2 * i + 1][1] = v1 + hB.y;
        upk2(acc[i][2], v0, v1); v[2 * i][2] = v0 + hA.z; v[2 * i + 1][2] = v1 + hB.z;
        upk2(acc[i][3], v0, v1); v[2 * i][3] = v0 + hA.w; v[2 * i + 1][3] = v1 + hB.w;
    }

    float4 g4 = __ldg((const float4*)(lng + tx * 4));
    float4 b4 = __ldg((const float4*)(lnb + tx * 4));
#pragma unroll
    for (int rr = 0; rr < 8; rr++) {
        float s = v[rr][0] + v[rr][1] + v[rr][2] + v[rr][3];
        float q = v[rr][0] * v[rr][0] + v[rr][1] * v[rr][1] +
                  v[rr][2] * v[rr][2] + v[rr][3] * v[rr][3];
#pragma unroll
        for (int off = 16; off > 0; off >>= 1) {
            s += __shfl_xor_sync(0xffffffffu, s, off);
            q += __shfl_xor_sync(0xffffffffu, q, off);
        }
        const float mu = s * (1.0f / 128.0f);
        const float var = q * (1.0f / 128.0f) - mu * mu;
        const float rstd = rsqrtf(var + 1e-5f);
        const int node = nb + r0 + rr;
        if (node < NNODES) {
            float4 o;
            o.x = (v[rr][0] - mu) * rstd * g4.x + b4.x;
            o.y = (v[rr][1] - mu) * rstd * g4.y + b4.y;
            o.z = (v[rr][2] - mu) * rstd * g4.z + b4.z;
            o.w = (v[rr][3] - mu) * rstd * g4.w + b4.w;
            *(float4*)(out_h + (long long)node * Hdim + tx * 4) = o;
        }
    }
}

// ---------- launch ----------
extern "C" void kernel_launch(void* const* d_in, const int* in_sizes, int n_in,
                              void* d_out, int out_size) {
    const float* h   = (const float*)d_in[0];
    const float* x   = (const float*)d_in[1];
    const void*  ei  = d_in[2];
    const float* We1 = (const float*)d_in[3];
    const float* be1 = (const float*)d_in[4];
    const float* We2 = (const float*)d_in[5];
    const float* be2 = (const float*)d_in[6];
    const float* Wc1 = (const float*)d_in[7];
    const float* bc1 = (const float*)d_in[8];
    const float* Wc2 = (const float*)d_in[9];
    const float* Wn1 = (const float*)d_in[10];
    const float* bn1 = (const float*)d_in[11];
    const float* Wn2 = (const float*)d_in[12];
    const float* bn2 = (const float*)d_in[13];
    const float* lng = (const float*)d_in[14];
    const float* lnb = (const float*)d_in[15];

    float* out_h = (float*)d_out;
    float* out_x = out_h + (long long)NNODES * Hdim;

    const int SMEM_PREP = BUF128 * 4;
    const int SMEM_NODE = (BUF256 + BUF128) * 4;

    cudaFuncSetAttribute(prep_kernel, cudaFuncAttributeMaxDynamicSharedMemorySize, SMEM_PREP);
    cudaFuncSetAttribute(edge_mma_kernel, cudaFuncAttributeMaxDynamicSharedMemorySize, EB_TOTAL);
    cudaFuncSetAttribute(node_kernel, cudaFuncAttributeMaxDynamicSharedMemorySize, SMEM_NODE);

    detect_kernel<<<1, 32>>>((const int*)ei);
    init_kernel<<<((long long)NNODES * Hdim + 255) / 256, 256>>>(x, out_x);
    prep_kernel<<<(NNODES + TILE - 1) / TILE, 256, SMEM_PREP>>>(h, We1, be1, We2, Wc1);
    edge_mma_kernel<<<NEDGES / ET, 128, EB_TOTAL>>>(x, ei, We1, be2, bc1, Wc2, out_x);
    node_kernel<<<(NNODES + TILE - 1) / TILE, 256, SMEM_NODE>>>(h, Wn1, bn1, Wn2, bn2,
                                                                lng, lnb, out_h);
}